// round 10
// baseline (speedup 1.0000x reference)
#include <cuda_runtime.h>
#include <cuda_fp16.h>
#include <math.h>
#include <stdint.h>

#define D   256
#define DI  512
#define NH  4
#define DH  128
#define NL  4
#define KC  4
#define NB  8
#define SS  1024
#define NT  (NB*SS)
#define NBH (NB*NH)

// ---------------- scratch ----------------
__device__ float g_h [NT*D];
__device__ float g_up[NT*2*DI];
__device__ float g_xc[NT*DI];
__device__ float g_htp[2*NT*DI];
__device__ float g_rs [2*NBH*SS];
__device__ float g_gates[NT*2*NH];
__device__ float g_alpha[NBH*SS];
__device__ float g_beta [NBH*SS];
__device__ float g_m    [NBH*SS];
__device__ float g_wc   [NL*DI*16];

__device__ __half g_hn_h[NT*D],  g_hn_l[NT*D];
__device__ __half g_xc_h[NT*DI], g_xc_l[NT*DI];
__device__ __half g_xm_h[NT*DI], g_xm_l[NT*DI];
__device__ __half g_mix_h[NT*DI], g_mix_l[NT*DI];
__device__ __half g_qh[NT*DI], g_ql[NT*DI];
__device__ __half g_kh[NT*DI];
__device__ __half g_vh[NT*DI];

#define WT_UP_OFF   0
#define WT_Q_OFF    262144
#define WT_K_OFF    524288
#define WT_V_OFF    786432
#define WT_DN_OFF   1048576
#define WT_L        1179648
__device__ __half g_wt_h[NL*WT_L];

__device__ __forceinline__ uint32_t smem_u32(const void* p) {
    uint32_t a;
    asm("{ .reg .u64 t; cvta.to.shared.u64 t, %1; cvt.u32.u64 %0, t; }" : "=r"(a) : "l"(p));
    return a;
}
__device__ __forceinline__ void ldmx4(uint32_t* r, uint32_t addr) {
    asm volatile("ldmatrix.sync.aligned.m8n8.x4.shared.b16 {%0,%1,%2,%3}, [%4];"
        : "=r"(r[0]), "=r"(r[1]), "=r"(r[2]), "=r"(r[3]) : "r"(addr));
}
__device__ __forceinline__ void mma16816(float* d, const uint32_t* a, const uint32_t* b) {
    asm volatile(
        "mma.sync.aligned.m16n8k16.row.col.f32.f16.f16.f32 "
        "{%0,%1,%2,%3}, {%4,%5,%6,%7}, {%8,%9}, {%0,%1,%2,%3};"
        : "+f"(d[0]), "+f"(d[1]), "+f"(d[2]), "+f"(d[3])
        : "r"(a[0]), "r"(a[1]), "r"(a[2]), "r"(a[3]), "r"(b[0]), "r"(b[1]));
}
__device__ __forceinline__ uint32_t packh2(float lo, float hi) {
    __half2 p = __floats2half2_rn(lo, hi);
    return *(uint32_t*)&p;
}
__device__ __forceinline__ void cpa16(uint32_t s, const void* g) {
    asm volatile("cp.async.cg.shared.global [%0], [%1], 16;" :: "r"(s), "l"(g));
}
#define CP_COMMIT() asm volatile("cp.async.commit_group;" ::: "memory")
#define CP_WAIT0()  asm volatile("cp.async.wait_group 0;" ::: "memory")

// ---------------- embed ----------------
__global__ void embed_kernel(const float* __restrict__ x, const float* __restrict__ tf,
                             const float* __restrict__ Wp, const float* __restrict__ bp) {
    int t = blockIdx.x, d = threadIdx.x;
    float acc = bp[d] + x[t] * Wp[d];
#pragma unroll
    for (int j = 0; j < 4; j++) acc += tf[t*4 + j] * Wp[(1+j)*D + d];
    g_h[t*D + d] = acc;
}

// ---------------- LayerNorm D=256 -> fp16 hi/lo ----------------
__global__ void ln256_kernel(const float* __restrict__ in, const float* __restrict__ g,
                             const float* __restrict__ b) {
    int t = blockIdx.x, tid = threadIdx.x;
    __shared__ float red[256];
    float v = in[t*256 + tid];
    red[tid] = v; __syncthreads();
    for (int off = 128; off > 0; off >>= 1) { if (tid < off) red[tid] += red[tid+off]; __syncthreads(); }
    float mean = red[0] * (1.f/256.f); __syncthreads();
    float c = v - mean;
    red[tid] = c*c; __syncthreads();
    for (int off = 128; off > 0; off >>= 1) { if (tid < off) red[tid] += red[tid+off]; __syncthreads(); }
    float var = red[0] * (1.f/256.f);
    float y = c * rsqrtf(var + 1e-5f) * g[tid] + b[tid];
    __half h = __float2half_rn(y);
    g_hn_h[t*256 + tid] = h;
    g_hn_l[t*256 + tid] = __float2half_rn(y - __half2float(h));
}

// ---------------- batched weight transpose ----------------
__global__ void wsplit_all(const float* __restrict__ Wbase, long wstride, int K, int N,
                           __half* __restrict__ th, long ostride) {
    __shared__ float tile[32][33];
    int l = blockIdx.z;
    const float* W = Wbase + (size_t)l*wstride;
    __half* out = th + (size_t)l*ostride;
    int k0 = blockIdx.x*32, n0 = blockIdx.y*32;
    int tx = threadIdx.x, ty = threadIdx.y;
    for (int i = ty; i < 32; i += 8)
        tile[i][tx] = W[(size_t)(k0+i)*N + n0 + tx];
    __syncthreads();
    for (int i = ty; i < 32; i += 8)
        out[(size_t)(n0+i)*K + k0 + tx] = __float2half_rn(tile[tx][i]);
}

// ---------------- combined gate weights ----------------
__global__ void wcomb_kernel(const float* __restrict__ Wq0, const float* __restrict__ Wk0,
                             const float* __restrict__ Wv0, const float* __restrict__ Wif0,
                             float* __restrict__ wc0) {
    int i = blockIdx.x, l = blockIdx.y;
    const float* Wq = Wq0 + (size_t)l*DI*DI;
    const float* Wk = Wk0 + (size_t)l*DI*DI;
    const float* Wv = Wv0 + (size_t)l*DI*DI;
    const float* Wif = Wif0 + (size_t)l*3*DI*8;
    float* wc = wc0 + (size_t)l*DI*16;
    int warp = threadIdx.x >> 5, lane = threadIdx.x & 31;
    float a1 = 0.f, a2 = 0.f;
    for (int j = lane; j < DI; j += 32) {
        a1 += Wq[(size_t)i*DI + j] * Wif[j*8 + warp]
            + Wk[(size_t)i*DI + j] * Wif[(DI + j)*8 + warp];
        a2 += Wv[(size_t)i*DI + j] * Wif[(2*DI + j)*8 + warp];
    }
#pragma unroll
    for (int d = 16; d > 0; d >>= 1) {
        a1 += __shfl_xor_sync(0xFFFFFFFFu, a1, d);
        a2 += __shfl_xor_sync(0xFFFFFFFFu, a2, d);
    }
    if (lane == 0) {
        wc[i*16 + warp] = a1;
        wc[i*16 + 8 + warp] = a2;
    }
}

// ---------------- fused conv+SiLU+gates: one block per token, 512 threads ----------------
__global__ void __launch_bounds__(512)
convgates_kernel(const float* __restrict__ w, const float* __restrict__ cbias,
                 const float* __restrict__ wc, const float* __restrict__ bif) {
    int t = blockIdx.x;
    int c = threadIdx.x;
    int s = t % SS;
    float acc = cbias[c];
#pragma unroll
    for (int j = 0; j < KC; j++) {
        int ss = s - 3 + j;
        if (ss >= 0) acc += g_up[(size_t)(t - 3 + j)*2*DI + c] * w[j*DI + c];
    }
    float y = acc / (1.f + __expf(-acc));
    size_t o = (size_t)t*DI + c;
    g_xc[o] = y;
    __half h = __float2half_rn(y);
    g_xc_h[o] = h;
    g_xc_l[o] = __float2half_rn(y - __half2float(h));

    float xmv = g_up[(size_t)t*2*DI + c];
    const float* wrow = wc + c*16;
    float p[8];
#pragma unroll
    for (int g = 0; g < 8; g++) p[g] = y*wrow[g] + xmv*wrow[8+g];
#pragma unroll
    for (int g = 0; g < 8; g++) {
#pragma unroll
        for (int d = 16; d > 0; d >>= 1) p[g] += __shfl_xor_sync(0xFFFFFFFFu, p[g], d);
    }
    __shared__ float red[16][8];
    int warp = c >> 5, lane = c & 31;
    if (lane == 0) {
#pragma unroll
        for (int g = 0; g < 8; g++) red[warp][g] = p[g];
    }
    __syncthreads();
    if (warp == 0 && lane < 8) {
        float a = 0.f;
#pragma unroll
        for (int w2 = 0; w2 < 16; w2++) a += red[w2][lane];
        g_gates[(size_t)t*8 + lane] = a + bif[lane];
    }
}

// ================= shared GEMM machinery =================
#define TSTR 40
#define OFF_AH 0
#define OFF_AL 10240
#define OFF_BH 20480
#define STAGE_B 30720
#define GEMM_SMEM (2*STAGE_B)

struct GemmCtx {
    uint32_t aoff[2][2], boff[4][2];
    uint32_t soA, soB;
    int wm, wn, lane;
};
__device__ __forceinline__ void gemm_init(GemmCtx& c, int tid) {
    int warp = tid >> 5; c.lane = tid & 31;
    c.wm = warp >> 1; c.wn = warp & 1;
#pragma unroll
    for (int mt = 0; mt < 2; mt++)
#pragma unroll
        for (int ks = 0; ks < 2; ks++)
            c.aoff[mt][ks] = ((c.wm*32 + mt*16 + (c.lane & 15))*TSTR + ks*16 + ((c.lane >> 4) << 3))*2;
#pragma unroll
    for (int ntp = 0; ntp < 4; ntp++)
#pragma unroll
        for (int ks = 0; ks < 2; ks++)
            c.boff[ntp][ks] = ((c.wn*64 + ntp*16 + ((c.lane >> 4) << 3) + (c.lane & 7))*TSTR
                               + ks*16 + (((c.lane >> 3) & 1) << 3))*2;
    int ldRow = tid >> 2, ldQuad = tid & 3;
    c.soA = (ldRow*TSTR + ldQuad*8)*2;
    c.soB = ((ldRow+64)*TSTR + ldQuad*8)*2;
}
__device__ __forceinline__ void gemm_stage(const GemmCtx& c, uint32_t st, int tid,
                                           const __half* Ah0, const __half* Al0, int lda,
                                           const __half* Bh0, int K, int k0) {
    int ldRow = tid >> 2, ldQuad = tid & 3;
    cpa16(st + OFF_AH + c.soA, Ah0 + (size_t)ldRow*lda + k0 + ldQuad*8);
    cpa16(st + OFF_AL + c.soA, Al0 + (size_t)ldRow*lda + k0 + ldQuad*8);
    cpa16(st + OFF_BH + c.soA, Bh0 + (size_t)ldRow*K + k0 + ldQuad*8);
    cpa16(st + OFF_AH + c.soB, Ah0 + (size_t)(ldRow+64)*lda + k0 + ldQuad*8);
    cpa16(st + OFF_AL + c.soB, Al0 + (size_t)(ldRow+64)*lda + k0 + ldQuad*8);
    cpa16(st + OFF_BH + c.soB, Bh0 + (size_t)(ldRow+64)*K + k0 + ldQuad*8);
    CP_COMMIT();
}
__device__ __forceinline__ void gemm_math(const GemmCtx& c, uint32_t st, float acc[2][8][4]) {
    uint32_t sAh_b = st + OFF_AH, sAl_b = st + OFF_AL, sBh_b = st + OFF_BH;
#pragma unroll
    for (int ks = 0; ks < 2; ks++) {
        uint32_t ah[2][4], al[2][4], bh[4][4];
#pragma unroll
        for (int mt = 0; mt < 2; mt++) {
            ldmx4(ah[mt], sAh_b + c.aoff[mt][ks]);
            ldmx4(al[mt], sAl_b + c.aoff[mt][ks]);
        }
#pragma unroll
        for (int ntp = 0; ntp < 4; ntp++)
            ldmx4(bh[ntp], sBh_b + c.boff[ntp][ks]);
#pragma unroll
        for (int mt = 0; mt < 2; mt++)
#pragma unroll
            for (int nt = 0; nt < 8; nt++) {
                int p = nt >> 1, hh = (nt & 1) * 2;
                mma16816(acc[mt][nt], ah[mt], &bh[p][hh]);
                mma16816(acc[mt][nt], al[mt], &bh[p][hh]);
            }
    }
}

// MODE: 0 fp32 (+bias,+resid) | 2 fp32 + hi/lo split for col<DI
template<int MODE>
__global__ void __launch_bounds__(256)
mmagemm2_kernel(const __half* __restrict__ Ah, const __half* __restrict__ Al, int lda,
                const __half* __restrict__ Bh,
                const float* __restrict__ bias, const float* __restrict__ resid,
                float* __restrict__ C, int ldc,
                __half* __restrict__ Ohi, __half* __restrict__ Olo, int ldo,
                int K) {
    extern __shared__ char dsm[];
    uint32_t sb = smem_u32(dsm);
    int tid = threadIdx.x;
    GemmCtx c; gemm_init(c, tid);
    int rowBase = blockIdx.x * 128;
    int colBase = blockIdx.y * 128;
    const __half* Ah0 = Ah + (size_t)rowBase*lda;
    const __half* Al0 = Al + (size_t)rowBase*lda;
    const __half* Bh0 = Bh + (size_t)colBase*K;

    float acc[2][8][4];
#pragma unroll
    for (int mt = 0; mt < 2; mt++)
#pragma unroll
        for (int nt = 0; nt < 8; nt++)
#pragma unroll
            for (int i = 0; i < 4; i++) acc[mt][nt][i] = 0.f;

    int nch = K >> 5;
    gemm_stage(c, sb, tid, Ah0, Al0, lda, Bh0, K, 0);
    int buf = 0;
    for (int ch = 0; ch < nch; ch++) {
        CP_WAIT0();
        __syncthreads();
        if (ch + 1 < nch)
            gemm_stage(c, sb + (buf^1)*STAGE_B, tid, Ah0, Al0, lda, Bh0, K, (ch+1) << 5);
        gemm_math(c, sb + buf*STAGE_B, acc);
        buf ^= 1;
        __syncthreads();
    }

    int r0b = rowBase + c.wm*32 + (c.lane >> 2);
    int cb  = colBase + c.wn*64 + (c.lane & 3)*2;
#pragma unroll
    for (int mt = 0; mt < 2; mt++) {
#pragma unroll
        for (int nt = 0; nt < 8; nt++) {
            int col = cb + nt*8;
#pragma unroll
            for (int half = 0; half < 2; half++) {
                int row = r0b + mt*16 + half*8;
                float vx = acc[mt][nt][half*2+0];
                float vy = acc[mt][nt][half*2+1];
                if (bias) { vx += bias[col]; vy += bias[col+1]; }
                if (MODE == 0 && resid) {
                    const float2 r2 = *(const float2*)(resid + (size_t)row*ldc + col);
                    vx += r2.x; vy += r2.y;
                }
                float2 o; o.x = vx; o.y = vy;
                *(float2*)(C + (size_t)row*ldc + col) = o;
                if (MODE == 2 && col < DI) {
                    __half hx = __float2half_rn(vx);
                    __half hy = __float2half_rn(vy);
                    __half2 hv; hv.x = hx; hv.y = hy;
                    __half2 lv;
                    lv.x = __float2half_rn(vx - __half2float(hx));
                    lv.y = __float2half_rn(vy - __half2float(hy));
                    *(__half2*)(Ohi + (size_t)row*ldo + col) = hv;
                    *(__half2*)(Olo + (size_t)row*ldo + col) = lv;
                }
            }
        }
    }
}

// ---------------- fused Q/K/V GEMM ----------------
__global__ void __launch_bounds__(256)
qkvgemm_kernel(const __half* __restrict__ wt) {
    extern __shared__ char dsm[];
    uint32_t sb = smem_u32(dsm);
    int tid = threadIdx.x;
    GemmCtx c; gemm_init(c, tid);
    int rowBase = blockIdx.x * 128;
    int yb = blockIdx.y;
    int sel = yb >> 2;
    int colBase = (yb & 3) * 128;

    const __half* Ah = (sel == 2) ? g_xm_h : g_xc_h;
    const __half* Al = (sel == 2) ? g_xm_l : g_xc_l;
    const __half* Bh0 = wt + (sel == 0 ? WT_Q_OFF : sel == 1 ? WT_K_OFF : WT_V_OFF)
                      + (size_t)colBase*DI;
    const __half* Ah0 = Ah + (size_t)rowBase*DI;
    const __half* Al0 = Al + (size_t)rowBase*DI;

    float acc[2][8][4];
#pragma unroll
    for (int mt = 0; mt < 2; mt++)
#pragma unroll
        for (int nt = 0; nt < 8; nt++)
#pragma unroll
            for (int i = 0; i < 4; i++) acc[mt][nt][i] = 0.f;

    gemm_stage(c, sb, tid, Ah0, Al0, DI, Bh0, DI, 0);
    int buf = 0;
    for (int ch = 0; ch < 16; ch++) {
        CP_WAIT0();
        __syncthreads();
        if (ch + 1 < 16)
            gemm_stage(c, sb + (buf^1)*STAGE_B, tid, Ah0, Al0, DI, Bh0, DI, (ch+1) << 5);
        gemm_math(c, sb + buf*STAGE_B, acc);
        buf ^= 1;
        __syncthreads();
    }

    __half* Ohi = (sel == 0) ? g_qh : (sel == 1) ? g_kh : g_vh;
    int r0b = rowBase + c.wm*32 + (c.lane >> 2);
    int cb  = colBase + c.wn*64 + (c.lane & 3)*2;
#pragma unroll
    for (int mt = 0; mt < 2; mt++) {
#pragma unroll
        for (int nt = 0; nt < 8; nt++) {
            int col = cb + nt*8;
#pragma unroll
            for (int half = 0; half < 2; half++) {
                int row = r0b + mt*16 + half*8;
                float vx = acc[mt][nt][half*2+0];
                float vy = acc[mt][nt][half*2+1];
                __half hx = __float2half_rn(vx);
                __half hy = __float2half_rn(vy);
                __half2 hv; hv.x = hx; hv.y = hy;
                *(__half2*)(Ohi + (size_t)row*DI + col) = hv;
                if (sel == 0) {
                    __half2 lv;
                    lv.x = __float2half_rn(vx - __half2float(hx));
                    lv.y = __float2half_rn(vy - __half2float(hy));
                    *(__half2*)(g_ql + (size_t)row*DI + col) = lv;
                }
            }
        }
    }
}

// ---------------- gate scan: smem preload + warp scan ----------------
__global__ void __launch_bounds__(256) gatescan_kernel() {
    __shared__ float sif[SS], sff[SS];
    int bh = blockIdx.x;
    int b = bh >> 2, h = bh & 3;
    int tid = threadIdx.x;
    for (int i = tid; i < SS; i += 256) {
        const float* gp = g_gates + (size_t)(b*SS + i)*8;
        sif[i] = gp[h];
        sff[i] = gp[NH + h];
    }
    __syncthreads();
    if (tid < 32) {
        int lane = tid;
        float carryF = 0.f, carryM = -1e30f;
        for (int c = 0; c < SS/32; c++) {
            int t = c*32 + lane;
            float fp = sff[t], ipv = sif[t];
            float lf = (fp >= 0.f) ? -log1pf(__expf(-fp)) : fp - log1pf(__expf(fp));
            float s = lf;
#pragma unroll
            for (int d = 1; d < 32; d <<= 1) {
                float v = __shfl_up_sync(0xFFFFFFFFu, s, d);
                if (lane >= d) s += v;
            }
            float Fc = carryF + s;
            float bt = ipv - Fc;
            float mx = bt;
#pragma unroll
            for (int d = 1; d < 32; d <<= 1) {
                float v = __shfl_up_sync(0xFFFFFFFFu, mx, d);
                if (lane >= d) mx = fmaxf(mx, v);
            }
            float rmax = fmaxf(carryM, mx);
            g_beta [bh*SS + t] = bt;
            g_alpha[bh*SS + t] = -rmax;
            g_m    [bh*SS + t] = Fc + rmax;
            carryF += __shfl_sync(0xFFFFFFFFu, s, 31);
            carryM  = fmaxf(carryM, __shfl_sync(0xFFFFFFFFu, rmax, 31));
        }
    }
}

// ================= split-s fp16 attention, heavy-blocks-first =================
#define STRQ 136
#define STRV 40
#define A2_QH 0
#define A2_QL (A2_QH + 128*STRQ*2)
#define A2_KH (A2_QL + 128*STRQ*2)
#define A2_VH (A2_KH + 32*STRQ*2)
#define A2_BT (A2_VH + 128*STRV*2)
#define ATTN2_SMEM (A2_BT + 32*4)
#define SCALE 0.08838834764831845f

__global__ void __launch_bounds__(256) attn2_kernel() {
    extern __shared__ char sm2[];
    __half* Qh = (__half*)(sm2 + A2_QH);
    __half* Ql = (__half*)(sm2 + A2_QL);
    __half* Kh = (__half*)(sm2 + A2_KH);
    __half* Vh = (__half*)(sm2 + A2_VH);
    float* bts = (float*)(sm2 + A2_BT);

    // heavy-first dispatch: qt descends as blockIdx.x ascends
    int xw = blockIdx.x;
    int qt = 7 - (xw >> 1);
    int sh = xw & 1;
    int bh = blockIdx.y;
    int b = bh >> 2, h = bh & 3;
    int tid = threadIdx.x, warp = tid >> 5, lane = tid & 31;
    int t0 = qt * 128;

#pragma unroll
    for (int j = 0; j < 8; j++) {
        int i = tid + j*256;
        int row = i >> 4, c8 = (i & 15)*8;
        size_t gb = (size_t)(b*SS + t0 + row)*DI + h*DH + c8;
        *(uint4*)(Qh + row*STRQ + c8) = *(const uint4*)(g_qh + gb);
        *(uint4*)(Ql + row*STRQ + c8) = *(const uint4*)(g_ql + gb);
    }

    int tr0 = t0 + warp*16 + (lane >> 2);
    int tr1 = tr0 + 8;
    float al0 = g_alpha[bh*SS + tr0];
    float al1 = g_alpha[bh*SS + tr1];

    float O[16][4];
#pragma unroll
    for (int nt = 0; nt < 16; nt++)
#pragma unroll
        for (int i = 0; i < 4; i++) O[nt][i] = 0.f;
    float rs0 = 0.f, rs1 = 0.f;

    uint32_t sQh = smem_u32(Qh), sQl = smem_u32(Ql);
    uint32_t sKh = smem_u32(Kh), sVh = smem_u32(Vh);

    uint32_t qoff[8], koff[2][8], voff[8][2];
#pragma unroll
    for (int ks = 0; ks < 8; ks++)
        qoff[ks] = ((warp*16 + (lane & 15))*STRQ + ks*16 + ((lane >> 4) << 3))*2;
#pragma unroll
    for (int np = 0; np < 2; np++)
#pragma unroll
        for (int ks = 0; ks < 8; ks++)
            koff[np][ks] = ((np*16 + ((lane >> 4) << 3) + (lane & 7))*STRQ
                            + ks*16 + (((lane >> 3) & 1) << 3))*2;
#pragma unroll
    for (int np = 0; np < 8; np++)
#pragma unroll
        for (int kv = 0; kv < 2; kv++)
            voff[np][kv] = ((np*16 + ((lane >> 4) << 3) + (lane & 7))*STRV
                            + kv*16 + (((lane >> 3) & 1) << 3))*2;

    int half_tiles = 2*(qt + 1);
    int st_lo = sh * half_tiles;
    int st_hi = st_lo + half_tiles;
    for (int st = st_lo; st < st_hi; st++) {
        int s0 = st * 32;
        __syncthreads();
#pragma unroll
        for (int j = 0; j < 2; j++) {
            int i = tid + j*256;
            int row = i >> 4, c8 = (i & 15)*8;
            size_t gb = (size_t)(b*SS + s0 + row)*DI + h*DH + c8;
            *(uint4*)(Kh + row*STRQ + c8) = *(const uint4*)(g_kh + gb);
            uint4 vh4 = *(const uint4*)(g_vh + gb);
            const __half* vhp = (const __half*)&vh4;
#pragma unroll
            for (int e = 0; e < 8; e++)
                Vh[(c8+e)*STRV + row] = vhp[e];
        }
        if (tid < 32) bts[tid] = g_beta[bh*SS + s0 + tid];
        __syncthreads();

        float S[4][4];
#pragma unroll
        for (int nt = 0; nt < 4; nt++)
#pragma unroll
            for (int i = 0; i < 4; i++) S[nt][i] = 0.f;
#pragma unroll
        for (int ks = 0; ks < 8; ks++) {
            uint32_t ah[4], al[4], bkh[2][4];
            ldmx4(ah, sQh + qoff[ks]);
            ldmx4(al, sQl + qoff[ks]);
            ldmx4(bkh[0], sKh + koff[0][ks]);
            ldmx4(bkh[1], sKh + koff[1][ks]);
#pragma unroll
            for (int nt = 0; nt < 4; nt++) {
                int p = nt >> 1, hh = (nt & 1)*2;
                mma16816(S[nt], ah, &bkh[p][hh]);
                mma16816(S[nt], al, &bkh[p][hh]);
            }
        }

        uint32_t Ph[2][4], Pl[2][4];
#pragma unroll
        for (int nt = 0; nt < 4; nt++) {
            float pv[4], plv[4];
#pragma unroll
            for (int r = 0; r < 4; r++) {
                int trow = (r < 2) ? tr0 : tr1;
                float alv = (r < 2) ? al0 : al1;
                int cl = nt*8 + (lane & 3)*2 + (r & 1);
                int sc = s0 + cl;
                float w = (sc <= trow) ? __expf(alv + bts[cl]) : 0.f;
                float p = S[nt][r] * SCALE * w;
                if (r < 2) rs0 += p; else rs1 += p;
                pv[r] = p;
                float ph = __half2float(__float2half_rn(p));
                plv[r] = p - ph;
            }
            int kv = nt >> 1;
            if ((nt & 1) == 0) {
                Ph[kv][0] = packh2(pv[0], pv[1]);
                Ph[kv][1] = packh2(pv[2], pv[3]);
                Pl[kv][0] = packh2(plv[0], plv[1]);
                Pl[kv][1] = packh2(plv[2], plv[3]);
            } else {
                Ph[kv][2] = packh2(pv[0], pv[1]);
                Ph[kv][3] = packh2(pv[2], pv[3]);
                Pl[kv][2] = packh2(plv[0], plv[1]);
                Pl[kv][3] = packh2(plv[2], plv[3]);
            }
        }

#pragma unroll
        for (int kv = 0; kv < 2; kv++) {
#pragma unroll
            for (int np = 0; np < 8; np++) {
                uint32_t bvh[4];
                ldmx4(bvh, sVh + voff[np][kv]);
#pragma unroll
                for (int hh = 0; hh < 2; hh++) {
                    int nt = np*2 + hh;
                    mma16816(O[nt], Ph[kv], &bvh[hh*2]);
                    mma16816(O[nt], Pl[kv], &bvh[hh*2]);
                }
            }
        }
    }

    rs0 += __shfl_xor_sync(0xFFFFFFFFu, rs0, 1);
    rs0 += __shfl_xor_sync(0xFFFFFFFFu, rs0, 2);
    rs1 += __shfl_xor_sync(0xFFFFFFFFu, rs1, 1);
    rs1 += __shfl_xor_sync(0xFFFFFFFFu, rs1, 2);
    if ((lane & 3) == 0) {
        g_rs[sh*NBH*SS + bh*SS + tr0] = rs0;
        g_rs[sh*NBH*SS + bh*SS + tr1] = rs1;
    }

    float* o0 = g_htp + (size_t)sh*NT*DI + (size_t)(b*SS + tr0)*DI + h*DH + (lane & 3)*2;
    float* o1 = g_htp + (size_t)sh*NT*DI + (size_t)(b*SS + tr1)*DI + h*DH + (lane & 3)*2;
#pragma unroll
    for (int nt = 0; nt < 16; nt++) {
        float2 v0; v0.x = O[nt][0]; v0.y = O[nt][1];
        float2 v1; v1.x = O[nt][2]; v1.y = O[nt][3];
        *(float2*)(o0 + nt*8) = v0;
        *(float2*)(o1 + nt*8) = v1;
    }
}

// ---------------- combine partials + per-head LN + skip + SiLU gate ----------------
__global__ void gnmerge_kernel(const float* __restrict__ gn_g, const float* __restrict__ gn_b,
                               const float* __restrict__ skip) {
    int t = blockIdx.x, tid = threadIdx.x;
    __shared__ float red[512];
    int l = tid & 127;
    int gbase = (tid >> 7) << 7;
    int b = t >> 10, s = t & 1023;
    int h = tid >> 7;
    int bh = b*NH + h;
    float rs = g_rs[bh*SS + s] + g_rs[NBH*SS + bh*SS + s];
    float me = __expf(-g_m[bh*SS + s]);
    float inv = 1.f / (fmaxf(fabsf(rs), me) + 1e-6f);
    float v = (g_htp[(size_t)t*DI + tid] + g_htp[(size_t)NT*DI + (size_t)t*DI + tid]) * inv;
    red[tid] = v; __syncthreads();
    for (int off = 64; off > 0; off >>= 1) { if (l < off) red[tid] += red[tid+off]; __syncthreads(); }
    float mean = red[gbase] * (1.f/128.f); __syncthreads();
    float c = v - mean;
    red[tid] = c*c; __syncthreads();
    for (int off = 64; off > 0; off >>= 1) { if (l < off) red[tid] += red[tid+off]; __syncthreads(); }
    float var = red[gbase] * (1.f/128.f);
    float y = c * rsqrtf(var + 1e-5f) * gn_g[tid] + gn_b[tid];
    y += skip[tid] * g_xc[(size_t)t*DI + tid];
    float z = g_up[(size_t)t*2*DI + DI + tid];
    y *= z / (1.f + __expf(-z));
    __half hh = __float2half_rn(y);
    g_mix_h[(size_t)t*DI + tid] = hh;
    g_mix_l[(size_t)t*DI + tid] = __float2half_rn(y - __half2float(hh));
}

// ---------------- final LN + projection ----------------
__global__ void final_kernel(const float* __restrict__ lnf_g, const float* __restrict__ lnf_b,
                             const float* __restrict__ Wf, const float* __restrict__ bf,
                             float* __restrict__ out) {
    int b = blockIdx.x, tid = threadIdx.x;
    __shared__ float red[256];
    float v = g_h[(size_t)(b*SS + SS - 1)*D + tid];
    red[tid] = v; __syncthreads();
    for (int off = 128; off > 0; off >>= 1) { if (tid < off) red[tid] += red[tid+off]; __syncthreads(); }
    float mean = red[0] * (1.f/256.f); __syncthreads();
    float c = v - mean;
    red[tid] = c*c; __syncthreads();
    for (int off = 128; off > 0; off >>= 1) { if (tid < off) red[tid] += red[tid+off]; __syncthreads(); }
    float var = red[0] * (1.f/256.f); __syncthreads();
    float y = c * rsqrtf(var + 1e-5f) * lnf_g[tid] + lnf_b[tid];
    red[tid] = y * Wf[tid]; __syncthreads();
    for (int off = 128; off > 0; off >>= 1) { if (tid < off) red[tid] += red[tid+off]; __syncthreads(); }
    if (tid == 0) out[b] = red[0] + bf[0];
}

// ---------------- host ----------------
static float* symaddrf(const void* sym) {
    void* p = nullptr;
    cudaGetSymbolAddress(&p, sym);
    return (float*)p;
}
static __half* symaddrh(const void* sym) {
    void* p = nullptr;
    cudaGetSymbolAddress(&p, sym);
    return (__half*)p;
}

extern "C" void kernel_launch(void* const* d_in, const int* in_sizes, int n_in,
                              void* d_out, int out_size) {
    const float* x      = (const float*)d_in[0];
    const float* tf     = (const float*)d_in[1];
    const float* Wp     = (const float*)d_in[2];
    const float* bp     = (const float*)d_in[3];
    const float* ln_g   = (const float*)d_in[4];
    const float* ln_b   = (const float*)d_in[5];
    const float* Wup    = (const float*)d_in[6];
    const float* bup    = (const float*)d_in[7];
    const float* conv_w = (const float*)d_in[8];
    const float* conv_b = (const float*)d_in[9];
    const float* Wq     = (const float*)d_in[10];
    const float* Wk     = (const float*)d_in[11];
    const float* Wv     = (const float*)d_in[12];
    const float* Wif    = (const float*)d_in[13];
    const float* bif    = (const float*)d_in[14];
    const float* gn_g   = (const float*)d_in[15];
    const float* gn_b   = (const float*)d_in[16];
    const float* skip   = (const float*)d_in[17];
    const float* Wdown  = (const float*)d_in[18];
    const float* bdown  = (const float*)d_in[19];
    const float* lnf_g  = (const float*)d_in[20];
    const float* lnf_b  = (const float*)d_in[21];
    const float* Wf     = (const float*)d_in[22];
    const float* bf     = (const float*)d_in[23];
    float* out = (float*)d_out;

    float* p_h   = symaddrf(g_h);
    float* p_up  = symaddrf(g_up);
    float* p_wc  = symaddrf(g_wc);
    __half* p_hn_h = symaddrh(g_hn_h);
    __half* p_hn_l = symaddrh(g_hn_l);
    __half* p_xm_h = symaddrh(g_xm_h);
    __half* p_xm_l = symaddrh(g_xm_l);
    __half* p_mix_h = symaddrh(g_mix_h);
    __half* p_mix_l = symaddrh(g_mix_l);
    __half* p_wt_h = symaddrh(g_wt_h);

    cudaFuncSetAttribute(attn2_kernel, cudaFuncAttributeMaxDynamicSharedMemorySize, ATTN2_SMEM);
    cudaFuncSetAttribute(mmagemm2_kernel<0>, cudaFuncAttributeMaxDynamicSharedMemorySize, GEMM_SMEM);
    cudaFuncSetAttribute(mmagemm2_kernel<2>, cudaFuncAttributeMaxDynamicSharedMemorySize, GEMM_SMEM);
    cudaFuncSetAttribute(qkvgemm_kernel, cudaFuncAttributeMaxDynamicSharedMemorySize, GEMM_SMEM);

    dim3 wblk(32, 8);
    wsplit_all<<<dim3(D/32, 2*DI/32, NL), wblk>>>(Wup, (long)D*2*DI, D, 2*DI,
                                                  p_wt_h + WT_UP_OFF, WT_L);
    wsplit_all<<<dim3(DI/32, DI/32, NL), wblk>>>(Wq, (long)DI*DI, DI, DI,
                                                 p_wt_h + WT_Q_OFF, WT_L);
    wsplit_all<<<dim3(DI/32, DI/32, NL), wblk>>>(Wk, (long)DI*DI, DI, DI,
                                                 p_wt_h + WT_K_OFF, WT_L);
    wsplit_all<<<dim3(DI/32, DI/32, NL), wblk>>>(Wv, (long)DI*DI, DI, DI,
                                                 p_wt_h + WT_V_OFF, WT_L);
    wsplit_all<<<dim3(DI/32, D/32, NL), wblk>>>(Wdown, (long)DI*D, DI, D,
                                                p_wt_h + WT_DN_OFF, WT_L);
    wcomb_kernel<<<dim3(DI, NL), 256>>>(Wq, Wk, Wv, Wif, p_wc);

    embed_kernel<<<NT, 256>>>(x, tf, Wp, bp);

    for (int l = 0; l < NL; l++) {
        size_t wo = (size_t)l * WT_L;
        ln256_kernel<<<NT, 256>>>(p_h, ln_g + l*D, ln_b + l*D);

        mmagemm2_kernel<2><<<dim3(NT/128, 1024/128), 256, GEMM_SMEM>>>(
            p_hn_h, p_hn_l, D, p_wt_h + wo + WT_UP_OFF,
            bup + l*2*DI, nullptr, p_up, 2*DI, p_xm_h, p_xm_l, DI, D);

        convgates_kernel<<<NT, 512>>>(conv_w + l*KC*DI, conv_b + l*DI,
                                      p_wc + (size_t)l*DI*16, bif + l*2*NH);

        qkvgemm_kernel<<<dim3(NT/128, 12), 256, GEMM_SMEM>>>(p_wt_h + wo);

        gatescan_kernel<<<NBH, 256>>>();

        attn2_kernel<<<dim3(16, NBH), 256, ATTN2_SMEM>>>();

        gnmerge_kernel<<<NT, 512>>>(gn_g + l*DI, gn_b + l*DI, skip + l*DI);

        mmagemm2_kernel<0><<<dim3(NT/128, D/128), 256, GEMM_SMEM>>>(
            p_mix_h, p_mix_l, DI, p_wt_h + wo + WT_DN_OFF,
            bdown + l*D, p_h, p_h, D, nullptr, nullptr, 0, DI);
    }

    final_kernel<<<NB, 256>>>(lnf_g, lnf_b, Wf, bf, out);
}

// round 12
// speedup vs baseline: 1.0372x; 1.0372x over previous
#include <cuda_runtime.h>
#include <cuda_fp16.h>
#include <math.h>
#include <stdint.h>

#define D   256
#define DI  512
#define NH  4
#define DH  128
#define NL  4
#define KC  4
#define NB  8
#define SS  1024
#define NT  (NB*SS)
#define NBH (NB*NH)

// ---------------- scratch ----------------
__device__ float g_h [NT*D];
__device__ float g_up[NT*2*DI];
__device__ float g_xc[NT*DI];
__device__ float g_htp[2*NT*DI];
__device__ float g_rs [2*NBH*SS];
__device__ float g_gates[NT*2*NH];
__device__ float g_alpha[NBH*SS];
__device__ float g_beta [NBH*SS];
__device__ float g_m    [NBH*SS];
__device__ float g_wc   [NL*DI*16];

__device__ __half g_hn_h[NT*D],  g_hn_l[NT*D];
__device__ __half g_xc_h[NT*DI], g_xc_l[NT*DI];
__device__ __half g_xm_h[NT*DI], g_xm_l[NT*DI];
__device__ __half g_mix_h[NT*DI], g_mix_l[NT*DI];
__device__ __half g_qh[NT*DI], g_ql[NT*DI];
__device__ __half g_kh[NT*DI];
__device__ __half g_vh[NT*DI];

#define WT_UP_OFF   0
#define WT_Q_OFF    262144
#define WT_K_OFF    524288
#define WT_V_OFF    786432
#define WT_DN_OFF   1048576
#define WT_L        1179648
__device__ __half g_wt_h[NL*WT_L];

__device__ __forceinline__ uint32_t smem_u32(const void* p) {
    uint32_t a;
    asm("{ .reg .u64 t; cvta.to.shared.u64 t, %1; cvt.u32.u64 %0, t; }" : "=r"(a) : "l"(p));
    return a;
}
__device__ __forceinline__ void ldmx4(uint32_t* r, uint32_t addr) {
    asm volatile("ldmatrix.sync.aligned.m8n8.x4.shared.b16 {%0,%1,%2,%3}, [%4];"
        : "=r"(r[0]), "=r"(r[1]), "=r"(r[2]), "=r"(r[3]) : "r"(addr));
}
__device__ __forceinline__ void mma16816(float* d, const uint32_t* a, const uint32_t* b) {
    asm volatile(
        "mma.sync.aligned.m16n8k16.row.col.f32.f16.f16.f32 "
        "{%0,%1,%2,%3}, {%4,%5,%6,%7}, {%8,%9}, {%0,%1,%2,%3};"
        : "+f"(d[0]), "+f"(d[1]), "+f"(d[2]), "+f"(d[3])
        : "r"(a[0]), "r"(a[1]), "r"(a[2]), "r"(a[3]), "r"(b[0]), "r"(b[1]));
}
__device__ __forceinline__ uint32_t packh2(float lo, float hi) {
    __half2 p = __floats2half2_rn(lo, hi);
    return *(uint32_t*)&p;
}
__device__ __forceinline__ void cpa16(uint32_t s, const void* g) {
    asm volatile("cp.async.cg.shared.global [%0], [%1], 16;" :: "r"(s), "l"(g));
}
#define CP_COMMIT() asm volatile("cp.async.commit_group;" ::: "memory")
#define CP_WAIT0()  asm volatile("cp.async.wait_group 0;" ::: "memory")

// ---------------- embed ----------------
__global__ void embed_kernel(const float* __restrict__ x, const float* __restrict__ tf,
                             const float* __restrict__ Wp, const float* __restrict__ bp) {
    int t = blockIdx.x, d = threadIdx.x;
    float acc = bp[d] + x[t] * Wp[d];
#pragma unroll
    for (int j = 0; j < 4; j++) acc += tf[t*4 + j] * Wp[(1+j)*D + d];
    g_h[t*D + d] = acc;
}

// ---------------- LayerNorm D=256 -> fp16 hi/lo ----------------
__global__ void ln256_kernel(const float* __restrict__ in, const float* __restrict__ g,
                             const float* __restrict__ b) {
    int t = blockIdx.x, tid = threadIdx.x;
    __shared__ float red[256];
    float v = in[t*256 + tid];
    red[tid] = v; __syncthreads();
    for (int off = 128; off > 0; off >>= 1) { if (tid < off) red[tid] += red[tid+off]; __syncthreads(); }
    float mean = red[0] * (1.f/256.f); __syncthreads();
    float c = v - mean;
    red[tid] = c*c; __syncthreads();
    for (int off = 128; off > 0; off >>= 1) { if (tid < off) red[tid] += red[tid+off]; __syncthreads(); }
    float var = red[0] * (1.f/256.f);
    float y = c * rsqrtf(var + 1e-5f) * g[tid] + b[tid];
    __half h = __float2half_rn(y);
    g_hn_h[t*256 + tid] = h;
    g_hn_l[t*256 + tid] = __float2half_rn(y - __half2float(h));
}

// ---------------- batched weight transpose ----------------
__global__ void wsplit_all(const float* __restrict__ Wbase, long wstride, int K, int N,
                           __half* __restrict__ th, long ostride) {
    __shared__ float tile[32][33];
    int l = blockIdx.z;
    const float* W = Wbase + (size_t)l*wstride;
    __half* out = th + (size_t)l*ostride;
    int k0 = blockIdx.x*32, n0 = blockIdx.y*32;
    int tx = threadIdx.x, ty = threadIdx.y;
    for (int i = ty; i < 32; i += 8)
        tile[i][tx] = W[(size_t)(k0+i)*N + n0 + tx];
    __syncthreads();
    for (int i = ty; i < 32; i += 8)
        out[(size_t)(n0+i)*K + k0 + tx] = __float2half_rn(tile[tx][i]);
}

// ---------------- combined gate weights ----------------
__global__ void wcomb_kernel(const float* __restrict__ Wq0, const float* __restrict__ Wk0,
                             const float* __restrict__ Wv0, const float* __restrict__ Wif0,
                             float* __restrict__ wc0) {
    int i = blockIdx.x, l = blockIdx.y;
    const float* Wq = Wq0 + (size_t)l*DI*DI;
    const float* Wk = Wk0 + (size_t)l*DI*DI;
    const float* Wv = Wv0 + (size_t)l*DI*DI;
    const float* Wif = Wif0 + (size_t)l*3*DI*8;
    float* wc = wc0 + (size_t)l*DI*16;
    int warp = threadIdx.x >> 5, lane = threadIdx.x & 31;
    float a1 = 0.f, a2 = 0.f;
    for (int j = lane; j < DI; j += 32) {
        a1 += Wq[(size_t)i*DI + j] * Wif[j*8 + warp]
            + Wk[(size_t)i*DI + j] * Wif[(DI + j)*8 + warp];
        a2 += Wv[(size_t)i*DI + j] * Wif[(2*DI + j)*8 + warp];
    }
#pragma unroll
    for (int d = 16; d > 0; d >>= 1) {
        a1 += __shfl_xor_sync(0xFFFFFFFFu, a1, d);
        a2 += __shfl_xor_sync(0xFFFFFFFFu, a2, d);
    }
    if (lane == 0) {
        wc[i*16 + warp] = a1;
        wc[i*16 + 8 + warp] = a2;
    }
}

// ---------------- gates ----------------
__global__ void gates2_kernel(const float* __restrict__ wc, const float* __restrict__ bif) {
    int warp = threadIdx.x >> 5, lane = threadIdx.x & 31;
    int t = blockIdx.x*8 + warp;
    float acc[8];
#pragma unroll
    for (int g = 0; g < 8; g++) acc[g] = 0.f;
    const float* xcr = g_xc + (size_t)t*DI;
    const float* xmr = g_up + (size_t)t*2*DI;
    for (int j = lane; j < DI; j += 32) {
        float xcv = xcr[j], xmv = xmr[j];
        const float* w = wc + j*16;
#pragma unroll
        for (int g = 0; g < 8; g++) acc[g] += xcv*w[g] + xmv*w[8+g];
    }
#pragma unroll
    for (int g = 0; g < 8; g++) {
#pragma unroll
        for (int d = 16; d > 0; d >>= 1) acc[g] += __shfl_xor_sync(0xFFFFFFFFu, acc[g], d);
    }
    if (lane < 8) g_gates[(size_t)t*8 + lane] = acc[lane] + bif[lane];
}

// ================= shared GEMM machinery =================
#define TSTR 40
#define OFF_AH 0
#define OFF_AL 10240
#define OFF_BH 20480
#define STAGE_B 30720
#define GEMM_SMEM (2*STAGE_B)

struct GemmCtx {
    uint32_t aoff[2][2], boff[4][2];
    uint32_t soA, soB;
    int wm, wn, lane;
};
__device__ __forceinline__ void gemm_init(GemmCtx& c, int tid) {
    int warp = tid >> 5; c.lane = tid & 31;
    c.wm = warp >> 1; c.wn = warp & 1;
#pragma unroll
    for (int mt = 0; mt < 2; mt++)
#pragma unroll
        for (int ks = 0; ks < 2; ks++)
            c.aoff[mt][ks] = ((c.wm*32 + mt*16 + (c.lane & 15))*TSTR + ks*16 + ((c.lane >> 4) << 3))*2;
#pragma unroll
    for (int ntp = 0; ntp < 4; ntp++)
#pragma unroll
        for (int ks = 0; ks < 2; ks++)
            c.boff[ntp][ks] = ((c.wn*64 + ntp*16 + ((c.lane >> 4) << 3) + (c.lane & 7))*TSTR
                               + ks*16 + (((c.lane >> 3) & 1) << 3))*2;
    int ldRow = tid >> 2, ldQuad = tid & 3;
    c.soA = (ldRow*TSTR + ldQuad*8)*2;
    c.soB = ((ldRow+64)*TSTR + ldQuad*8)*2;
}
__device__ __forceinline__ void gemm_stage(const GemmCtx& c, uint32_t st, int tid,
                                           const __half* Ah0, const __half* Al0, int lda,
                                           const __half* Bh0, int K, int k0) {
    int ldRow = tid >> 2, ldQuad = tid & 3;
    cpa16(st + OFF_AH + c.soA, Ah0 + (size_t)ldRow*lda + k0 + ldQuad*8);
    cpa16(st + OFF_AL + c.soA, Al0 + (size_t)ldRow*lda + k0 + ldQuad*8);
    cpa16(st + OFF_BH + c.soA, Bh0 + (size_t)ldRow*K + k0 + ldQuad*8);
    cpa16(st + OFF_AH + c.soB, Ah0 + (size_t)(ldRow+64)*lda + k0 + ldQuad*8);
    cpa16(st + OFF_AL + c.soB, Al0 + (size_t)(ldRow+64)*lda + k0 + ldQuad*8);
    cpa16(st + OFF_BH + c.soB, Bh0 + (size_t)(ldRow+64)*K + k0 + ldQuad*8);
    CP_COMMIT();
}
__device__ __forceinline__ void gemm_math(const GemmCtx& c, uint32_t st, float acc[2][8][4]) {
    uint32_t sAh_b = st + OFF_AH, sAl_b = st + OFF_AL, sBh_b = st + OFF_BH;
#pragma unroll
    for (int ks = 0; ks < 2; ks++) {
        uint32_t ah[2][4], al[2][4], bh[4][4];
#pragma unroll
        for (int mt = 0; mt < 2; mt++) {
            ldmx4(ah[mt], sAh_b + c.aoff[mt][ks]);
            ldmx4(al[mt], sAl_b + c.aoff[mt][ks]);
        }
#pragma unroll
        for (int ntp = 0; ntp < 4; ntp++)
            ldmx4(bh[ntp], sBh_b + c.boff[ntp][ks]);
#pragma unroll
        for (int mt = 0; mt < 2; mt++)
#pragma unroll
            for (int nt = 0; nt < 8; nt++) {
                int p = nt >> 1, hh = (nt & 1) * 2;
                mma16816(acc[mt][nt], ah[mt], &bh[p][hh]);
                mma16816(acc[mt][nt], al[mt], &bh[p][hh]);
            }
    }
}

// MODE: 0 fp32 (+bias,+resid) | 2 fp32 + hi/lo split for col<DI
template<int MODE>
__global__ void __launch_bounds__(256)
mmagemm2_kernel(const __half* __restrict__ Ah, const __half* __restrict__ Al, int lda,
                const __half* __restrict__ Bh,
                const float* __restrict__ bias, const float* __restrict__ resid,
                float* __restrict__ C, int ldc,
                __half* __restrict__ Ohi, __half* __restrict__ Olo, int ldo,
                int K) {
    extern __shared__ char dsm[];
    uint32_t sb = smem_u32(dsm);
    int tid = threadIdx.x;
    GemmCtx c; gemm_init(c, tid);
    int rowBase = blockIdx.x * 128;
    int colBase = blockIdx.y * 128;
    const __half* Ah0 = Ah + (size_t)rowBase*lda;
    const __half* Al0 = Al + (size_t)rowBase*lda;
    const __half* Bh0 = Bh + (size_t)colBase*K;

    float acc[2][8][4];
#pragma unroll
    for (int mt = 0; mt < 2; mt++)
#pragma unroll
        for (int nt = 0; nt < 8; nt++)
#pragma unroll
            for (int i = 0; i < 4; i++) acc[mt][nt][i] = 0.f;

    int nch = K >> 5;
    gemm_stage(c, sb, tid, Ah0, Al0, lda, Bh0, K, 0);
    int buf = 0;
    for (int ch = 0; ch < nch; ch++) {
        CP_WAIT0();
        __syncthreads();
        if (ch + 1 < nch)
            gemm_stage(c, sb + (buf^1)*STAGE_B, tid, Ah0, Al0, lda, Bh0, K, (ch+1) << 5);
        gemm_math(c, sb + buf*STAGE_B, acc);
        buf ^= 1;
        __syncthreads();
    }

    int r0b = rowBase + c.wm*32 + (c.lane >> 2);
    int cb  = colBase + c.wn*64 + (c.lane & 3)*2;
#pragma unroll
    for (int mt = 0; mt < 2; mt++) {
#pragma unroll
        for (int nt = 0; nt < 8; nt++) {
            int col = cb + nt*8;
#pragma unroll
            for (int half = 0; half < 2; half++) {
                int row = r0b + mt*16 + half*8;
                float vx = acc[mt][nt][half*2+0];
                float vy = acc[mt][nt][half*2+1];
                if (bias) { vx += bias[col]; vy += bias[col+1]; }
                if (MODE == 0 && resid) {
                    const float2 r2 = *(const float2*)(resid + (size_t)row*ldc + col);
                    vx += r2.x; vy += r2.y;
                }
                float2 o; o.x = vx; o.y = vy;
                *(float2*)(C + (size_t)row*ldc + col) = o;
                if (MODE == 2 && col < DI) {
                    __half hx = __float2half_rn(vx);
                    __half hy = __float2half_rn(vy);
                    __half2 hv; hv.x = hx; hv.y = hy;
                    __half2 lv;
                    lv.x = __float2half_rn(vx - __half2float(hx));
                    lv.y = __float2half_rn(vy - __half2float(hy));
                    *(__half2*)(Ohi + (size_t)row*ldo + col) = hv;
                    *(__half2*)(Olo + (size_t)row*ldo + col) = lv;
                }
            }
        }
    }
}

// ---------------- fused Q/K/V GEMM ----------------
__global__ void __launch_bounds__(256)
qkvgemm_kernel(const __half* __restrict__ wt) {
    extern __shared__ char dsm[];
    uint32_t sb = smem_u32(dsm);
    int tid = threadIdx.x;
    GemmCtx c; gemm_init(c, tid);
    int rowBase = blockIdx.x * 128;
    int yb = blockIdx.y;
    int sel = yb >> 2;
    int colBase = (yb & 3) * 128;

    const __half* Ah = (sel == 2) ? g_xm_h : g_xc_h;
    const __half* Al = (sel == 2) ? g_xm_l : g_xc_l;
    const __half* Bh0 = wt + (sel == 0 ? WT_Q_OFF : sel == 1 ? WT_K_OFF : WT_V_OFF)
                      + (size_t)colBase*DI;
    const __half* Ah0 = Ah + (size_t)rowBase*DI;
    const __half* Al0 = Al + (size_t)rowBase*DI;

    float acc[2][8][4];
#pragma unroll
    for (int mt = 0; mt < 2; mt++)
#pragma unroll
        for (int nt = 0; nt < 8; nt++)
#pragma unroll
            for (int i = 0; i < 4; i++) acc[mt][nt][i] = 0.f;

    gemm_stage(c, sb, tid, Ah0, Al0, DI, Bh0, DI, 0);
    int buf = 0;
    for (int ch = 0; ch < 16; ch++) {
        CP_WAIT0();
        __syncthreads();
        if (ch + 1 < 16)
            gemm_stage(c, sb + (buf^1)*STAGE_B, tid, Ah0, Al0, DI, Bh0, DI, (ch+1) << 5);
        gemm_math(c, sb + buf*STAGE_B, acc);
        buf ^= 1;
        __syncthreads();
    }

    __half* Ohi = (sel == 0) ? g_qh : (sel == 1) ? g_kh : g_vh;
    int r0b = rowBase + c.wm*32 + (c.lane >> 2);
    int cb  = colBase + c.wn*64 + (c.lane & 3)*2;
#pragma unroll
    for (int mt = 0; mt < 2; mt++) {
#pragma unroll
        for (int nt = 0; nt < 8; nt++) {
            int col = cb + nt*8;
#pragma unroll
            for (int half = 0; half < 2; half++) {
                int row = r0b + mt*16 + half*8;
                float vx = acc[mt][nt][half*2+0];
                float vy = acc[mt][nt][half*2+1];
                __half hx = __float2half_rn(vx);
                __half hy = __float2half_rn(vy);
                __half2 hv; hv.x = hx; hv.y = hy;
                *(__half2*)(Ohi + (size_t)row*DI + col) = hv;
                if (sel == 0) {
                    __half2 lv;
                    lv.x = __float2half_rn(vx - __half2float(hx));
                    lv.y = __float2half_rn(vy - __half2float(hy));
                    *(__half2*)(g_ql + (size_t)row*DI + col) = lv;
                }
            }
        }
    }
}

// ---------------- conv + SiLU ----------------
__global__ void conv_kernel(const float* __restrict__ w, const float* __restrict__ bias) {
    int idx = blockIdx.x * blockDim.x + threadIdx.x;
    int c = idx % DI;
    int t = idx / DI;
    int s = t % SS;
    float acc = bias[c];
#pragma unroll
    for (int j = 0; j < KC; j++) {
        int ss = s - 3 + j;
        if (ss >= 0) acc += g_up[(size_t)(t - 3 + j)*2*DI + c] * w[j*DI + c];
    }
    float y = acc / (1.f + __expf(-acc));
    g_xc[idx] = y;
    __half h = __float2half_rn(y);
    g_xc_h[idx] = h;
    g_xc_l[idx] = __float2half_rn(y - __half2float(h));
}

// ---------------- gate scan: smem preload + warp scan ----------------
__global__ void __launch_bounds__(256) gatescan_kernel() {
    __shared__ float sif[SS], sff[SS];
    int bh = blockIdx.x;
    int b = bh >> 2, h = bh & 3;
    int tid = threadIdx.x;
    for (int i = tid; i < SS; i += 256) {
        const float* gp = g_gates + (size_t)(b*SS + i)*8;
        sif[i] = gp[h];
        sff[i] = gp[NH + h];
    }
    __syncthreads();
    if (tid < 32) {
        int lane = tid;
        float carryF = 0.f, carryM = -1e30f;
        for (int c = 0; c < SS/32; c++) {
            int t = c*32 + lane;
            float fp = sff[t], ipv = sif[t];
            float lf = (fp >= 0.f) ? -log1pf(__expf(-fp)) : fp - log1pf(__expf(fp));
            float s = lf;
#pragma unroll
            for (int d = 1; d < 32; d <<= 1) {
                float v = __shfl_up_sync(0xFFFFFFFFu, s, d);
                if (lane >= d) s += v;
            }
            float Fc = carryF + s;
            float bt = ipv - Fc;
            float mx = bt;
#pragma unroll
            for (int d = 1; d < 32; d <<= 1) {
                float v = __shfl_up_sync(0xFFFFFFFFu, mx, d);
                if (lane >= d) mx = fmaxf(mx, v);
            }
            float rmax = fmaxf(carryM, mx);
            g_beta [bh*SS + t] = bt;
            g_alpha[bh*SS + t] = -rmax;
            g_m    [bh*SS + t] = Fc + rmax;
            carryF += __shfl_sync(0xFFFFFFFFu, s, 31);
            carryM  = fmaxf(carryM, __shfl_sync(0xFFFFFFFFu, rmax, 31));
        }
    }
}

// ================= split-s fp16 attention, heavy-blocks-first =================
#define STRQ 136
#define STRV 40
#define A2_QH 0
#define A2_QL (A2_QH + 128*STRQ*2)
#define A2_KH (A2_QL + 128*STRQ*2)
#define A2_VH (A2_KH + 32*STRQ*2)
#define A2_BT (A2_VH + 128*STRV*2)
#define ATTN2_SMEM (A2_BT + 32*4)
#define SCALE 0.08838834764831845f

__global__ void __launch_bounds__(256) attn2_kernel() {
    extern __shared__ char sm2[];
    __half* Qh = (__half*)(sm2 + A2_QH);
    __half* Ql = (__half*)(sm2 + A2_QL);
    __half* Kh = (__half*)(sm2 + A2_KH);
    __half* Vh = (__half*)(sm2 + A2_VH);
    float* bts = (float*)(sm2 + A2_BT);

    // heavy-first dispatch: qt descends as blockIdx.x ascends
    int xw = blockIdx.x;
    int qt = 7 - (xw >> 1);
    int sh = xw & 1;
    int bh = blockIdx.y;
    int b = bh >> 2, h = bh & 3;
    int tid = threadIdx.x, warp = tid >> 5, lane = tid & 31;
    int t0 = qt * 128;

#pragma unroll
    for (int j = 0; j < 8; j++) {
        int i = tid + j*256;
        int row = i >> 4, c8 = (i & 15)*8;
        size_t gb = (size_t)(b*SS + t0 + row)*DI + h*DH + c8;
        *(uint4*)(Qh + row*STRQ + c8) = *(const uint4*)(g_qh + gb);
        *(uint4*)(Ql + row*STRQ + c8) = *(const uint4*)(g_ql + gb);
    }

    int tr0 = t0 + warp*16 + (lane >> 2);
    int tr1 = tr0 + 8;
    float al0 = g_alpha[bh*SS + tr0];
    float al1 = g_alpha[bh*SS + tr1];

    float O[16][4];
#pragma unroll
    for (int nt = 0; nt < 16; nt++)
#pragma unroll
        for (int i = 0; i < 4; i++) O[nt][i] = 0.f;
    float rs0 = 0.f, rs1 = 0.f;

    uint32_t sQh = smem_u32(Qh), sQl = smem_u32(Ql);
    uint32_t sKh = smem_u32(Kh), sVh = smem_u32(Vh);

    uint32_t qoff[8], koff[2][8], voff[8][2];
#pragma unroll
    for (int ks = 0; ks < 8; ks++)
        qoff[ks] = ((warp*16 + (lane & 15))*STRQ + ks*16 + ((lane >> 4) << 3))*2;
#pragma unroll
    for (int np = 0; np < 2; np++)
#pragma unroll
        for (int ks = 0; ks < 8; ks++)
            koff[np][ks] = ((np*16 + ((lane >> 4) << 3) + (lane & 7))*STRQ
                            + ks*16 + (((lane >> 3) & 1) << 3))*2;
#pragma unroll
    for (int np = 0; np < 8; np++)
#pragma unroll
        for (int kv = 0; kv < 2; kv++)
            voff[np][kv] = ((np*16 + ((lane >> 4) << 3) + (lane & 7))*STRV
                            + kv*16 + (((lane >> 3) & 1) << 3))*2;

    int half_tiles = 2*(qt + 1);
    int st_lo = sh * half_tiles;
    int st_hi = st_lo + half_tiles;
    for (int st = st_lo; st < st_hi; st++) {
        int s0 = st * 32;
        __syncthreads();
#pragma unroll
        for (int j = 0; j < 2; j++) {
            int i = tid + j*256;
            int row = i >> 4, c8 = (i & 15)*8;
            size_t gb = (size_t)(b*SS + s0 + row)*DI + h*DH + c8;
            *(uint4*)(Kh + row*STRQ + c8) = *(const uint4*)(g_kh + gb);
            uint4 vh4 = *(const uint4*)(g_vh + gb);
            const __half* vhp = (const __half*)&vh4;
#pragma unroll
            for (int e = 0; e < 8; e++)
                Vh[(c8+e)*STRV + row] = vhp[e];
        }
        if (tid < 32) bts[tid] = g_beta[bh*SS + s0 + tid];
        __syncthreads();

        float S[4][4];
#pragma unroll
        for (int nt = 0; nt < 4; nt++)
#pragma unroll
            for (int i = 0; i < 4; i++) S[nt][i] = 0.f;
#pragma unroll
        for (int ks = 0; ks < 8; ks++) {
            uint32_t ah[4], al[4], bkh[2][4];
            ldmx4(ah, sQh + qoff[ks]);
            ldmx4(al, sQl + qoff[ks]);
            ldmx4(bkh[0], sKh + koff[0][ks]);
            ldmx4(bkh[1], sKh + koff[1][ks]);
#pragma unroll
            for (int nt = 0; nt < 4; nt++) {
                int p = nt >> 1, hh = (nt & 1)*2;
                mma16816(S[nt], ah, &bkh[p][hh]);
                mma16816(S[nt], al, &bkh[p][hh]);
            }
        }

        uint32_t Ph[2][4], Pl[2][4];
#pragma unroll
        for (int nt = 0; nt < 4; nt++) {
            float pv[4], plv[4];
#pragma unroll
            for (int r = 0; r < 4; r++) {
                int trow = (r < 2) ? tr0 : tr1;
                float alv = (r < 2) ? al0 : al1;
                int cl = nt*8 + (lane & 3)*2 + (r & 1);
                int sc = s0 + cl;
                float w = (sc <= trow) ? __expf(alv + bts[cl]) : 0.f;
                float p = S[nt][r] * SCALE * w;
                if (r < 2) rs0 += p; else rs1 += p;
                pv[r] = p;
                float ph = __half2float(__float2half_rn(p));
                plv[r] = p - ph;
            }
            int kv = nt >> 1;
            if ((nt & 1) == 0) {
                Ph[kv][0] = packh2(pv[0], pv[1]);
                Ph[kv][1] = packh2(pv[2], pv[3]);
                Pl[kv][0] = packh2(plv[0], plv[1]);
                Pl[kv][1] = packh2(plv[2], plv[3]);
            } else {
                Ph[kv][2] = packh2(pv[0], pv[1]);
                Ph[kv][3] = packh2(pv[2], pv[3]);
                Pl[kv][2] = packh2(plv[0], plv[1]);
                Pl[kv][3] = packh2(plv[2], plv[3]);
            }
        }

#pragma unroll
        for (int kv = 0; kv < 2; kv++) {
#pragma unroll
            for (int np = 0; np < 8; np++) {
                uint32_t bvh[4];
                ldmx4(bvh, sVh + voff[np][kv]);
#pragma unroll
                for (int hh = 0; hh < 2; hh++) {
                    int nt = np*2 + hh;
                    mma16816(O[nt], Ph[kv], &bvh[hh*2]);
                    mma16816(O[nt], Pl[kv], &bvh[hh*2]);
                }
            }
        }
    }

    rs0 += __shfl_xor_sync(0xFFFFFFFFu, rs0, 1);
    rs0 += __shfl_xor_sync(0xFFFFFFFFu, rs0, 2);
    rs1 += __shfl_xor_sync(0xFFFFFFFFu, rs1, 1);
    rs1 += __shfl_xor_sync(0xFFFFFFFFu, rs1, 2);
    if ((lane & 3) == 0) {
        g_rs[sh*NBH*SS + bh*SS + tr0] = rs0;
        g_rs[sh*NBH*SS + bh*SS + tr1] = rs1;
    }

    float* o0 = g_htp + (size_t)sh*NT*DI + (size_t)(b*SS + tr0)*DI + h*DH + (lane & 3)*2;
    float* o1 = g_htp + (size_t)sh*NT*DI + (size_t)(b*SS + tr1)*DI + h*DH + (lane & 3)*2;
#pragma unroll
    for (int nt = 0; nt < 16; nt++) {
        float2 v0; v0.x = O[nt][0]; v0.y = O[nt][1];
        float2 v1; v1.x = O[nt][2]; v1.y = O[nt][3];
        *(float2*)(o0 + nt*8) = v0;
        *(float2*)(o1 + nt*8) = v1;
    }
}

// ---------------- combine partials + per-head LN + skip + SiLU gate ----------------
__global__ void gnmerge_kernel(const float* __restrict__ gn_g, const float* __restrict__ gn_b,
                               const float* __restrict__ skip) {
    int t = blockIdx.x, tid = threadIdx.x;
    __shared__ float red[512];
    int l = tid & 127;
    int gbase = (tid >> 7) << 7;
    int b = t >> 10, s = t & 1023;
    int h = tid >> 7;
    int bh = b*NH + h;
    float rs = g_rs[bh*SS + s] + g_rs[NBH*SS + bh*SS + s];
    float me = __expf(-g_m[bh*SS + s]);
    float inv = 1.f / (fmaxf(fabsf(rs), me) + 1e-6f);
    float v = (g_htp[(size_t)t*DI + tid] + g_htp[(size_t)NT*DI + (size_t)t*DI + tid]) * inv;
    red[tid] = v; __syncthreads();
    for (int off = 64; off > 0; off >>= 1) { if (l < off) red[tid] += red[tid+off]; __syncthreads(); }
    float mean = red[gbase] * (1.f/128.f); __syncthreads();
    float c = v - mean;
    red[tid] = c*c; __syncthreads();
    for (int off = 64; off > 0; off >>= 1) { if (l < off) red[tid] += red[tid+off]; __syncthreads(); }
    float var = red[gbase] * (1.f/128.f);
    float y = c * rsqrtf(var + 1e-5f) * gn_g[tid] + gn_b[tid];
    y += skip[tid] * g_xc[(size_t)t*DI + tid];
    float z = g_up[(size_t)t*2*DI + DI + tid];
    y *= z / (1.f + __expf(-z));
    __half hh = __float2half_rn(y);
    g_mix_h[(size_t)t*DI + tid] = hh;
    g_mix_l[(size_t)t*DI + tid] = __float2half_rn(y - __half2float(hh));
}

// ---------------- final LN + projection ----------------
__global__ void final_kernel(const float* __restrict__ lnf_g, const float* __restrict__ lnf_b,
                             const float* __restrict__ Wf, const float* __restrict__ bf,
                             float* __restrict__ out) {
    int b = blockIdx.x, tid = threadIdx.x;
    __shared__ float red[256];
    float v = g_h[(size_t)(b*SS + SS - 1)*D + tid];
    red[tid] = v; __syncthreads();
    for (int off = 128; off > 0; off >>= 1) { if (tid < off) red[tid] += red[tid+off]; __syncthreads(); }
    float mean = red[0] * (1.f/256.f); __syncthreads();
    float c = v - mean;
    red[tid] = c*c; __syncthreads();
    for (int off = 128; off > 0; off >>= 1) { if (tid < off) red[tid] += red[tid+off]; __syncthreads(); }
    float var = red[0] * (1.f/256.f); __syncthreads();
    float y = c * rsqrtf(var + 1e-5f) * lnf_g[tid] + lnf_b[tid];
    red[tid] = y * Wf[tid]; __syncthreads();
    for (int off = 128; off > 0; off >>= 1) { if (tid < off) red[tid] += red[tid+off]; __syncthreads(); }
    if (tid == 0) out[b] = red[0] + bf[0];
}

// ---------------- host ----------------
static float* symaddrf(const void* sym) {
    void* p = nullptr;
    cudaGetSymbolAddress(&p, sym);
    return (float*)p;
}
static __half* symaddrh(const void* sym) {
    void* p = nullptr;
    cudaGetSymbolAddress(&p, sym);
    return (__half*)p;
}

extern "C" void kernel_launch(void* const* d_in, const int* in_sizes, int n_in,
                              void* d_out, int out_size) {
    const float* x      = (const float*)d_in[0];
    const float* tf     = (const float*)d_in[1];
    const float* Wp     = (const float*)d_in[2];
    const float* bp     = (const float*)d_in[3];
    const float* ln_g   = (const float*)d_in[4];
    const float* ln_b   = (const float*)d_in[5];
    const float* Wup    = (const float*)d_in[6];
    const float* bup    = (const float*)d_in[7];
    const float* conv_w = (const float*)d_in[8];
    const float* conv_b = (const float*)d_in[9];
    const float* Wq     = (const float*)d_in[10];
    const float* Wk     = (const float*)d_in[11];
    const float* Wv     = (const float*)d_in[12];
    const float* Wif    = (const float*)d_in[13];
    const float* bif    = (const float*)d_in[14];
    const float* gn_g   = (const float*)d_in[15];
    const float* gn_b   = (const float*)d_in[16];
    const float* skip   = (const float*)d_in[17];
    const float* Wdown  = (const float*)d_in[18];
    const float* bdown  = (const float*)d_in[19];
    const float* lnf_g  = (const float*)d_in[20];
    const float* lnf_b  = (const float*)d_in[21];
    const float* Wf     = (const float*)d_in[22];
    const float* bf     = (const float*)d_in[23];
    float* out = (float*)d_out;

    float* p_h   = symaddrf(g_h);
    float* p_up  = symaddrf(g_up);
    float* p_wc  = symaddrf(g_wc);
    __half* p_hn_h = symaddrh(g_hn_h);
    __half* p_hn_l = symaddrh(g_hn_l);
    __half* p_xm_h = symaddrh(g_xm_h);
    __half* p_xm_l = symaddrh(g_xm_l);
    __half* p_mix_h = symaddrh(g_mix_h);
    __half* p_mix_l = symaddrh(g_mix_l);
    __half* p_wt_h = symaddrh(g_wt_h);

    cudaFuncSetAttribute(attn2_kernel, cudaFuncAttributeMaxDynamicSharedMemorySize, ATTN2_SMEM);
    cudaFuncSetAttribute(mmagemm2_kernel<0>, cudaFuncAttributeMaxDynamicSharedMemorySize, GEMM_SMEM);
    cudaFuncSetAttribute(mmagemm2_kernel<2>, cudaFuncAttributeMaxDynamicSharedMemorySize, GEMM_SMEM);
    cudaFuncSetAttribute(qkvgemm_kernel, cudaFuncAttributeMaxDynamicSharedMemorySize, GEMM_SMEM);

    dim3 wblk(32, 8);
    wsplit_all<<<dim3(D/32, 2*DI/32, NL), wblk>>>(Wup, (long)D*2*DI, D, 2*DI,
                                                  p_wt_h + WT_UP_OFF, WT_L);
    wsplit_all<<<dim3(DI/32, DI/32, NL), wblk>>>(Wq, (long)DI*DI, DI, DI,
                                                 p_wt_h + WT_Q_OFF, WT_L);
    wsplit_all<<<dim3(DI/32, DI/32, NL), wblk>>>(Wk, (long)DI*DI, DI, DI,
                                                 p_wt_h + WT_K_OFF, WT_L);
    wsplit_all<<<dim3(DI/32, DI/32, NL), wblk>>>(Wv, (long)DI*DI, DI, DI,
                                                 p_wt_h + WT_V_OFF, WT_L);
    wsplit_all<<<dim3(DI/32, D/32, NL), wblk>>>(Wdown, (long)DI*D, DI, D,
                                                p_wt_h + WT_DN_OFF, WT_L);
    wcomb_kernel<<<dim3(DI, NL), 256>>>(Wq, Wk, Wv, Wif, p_wc);

    embed_kernel<<<NT, 256>>>(x, tf, Wp, bp);

    for (int l = 0; l < NL; l++) {
        size_t wo = (size_t)l * WT_L;
        ln256_kernel<<<NT, 256>>>(p_h, ln_g + l*D, ln_b + l*D);

        mmagemm2_kernel<2><<<dim3(NT/128, 1024/128), 256, GEMM_SMEM>>>(
            p_hn_h, p_hn_l, D, p_wt_h + wo + WT_UP_OFF,
            bup + l*2*DI, nullptr, p_up, 2*DI, p_xm_h, p_xm_l, DI, D);

        conv_kernel<<<NT*DI/256, 256>>>(conv_w + l*KC*DI, conv_b + l*DI);

        qkvgemm_kernel<<<dim3(NT/128, 12), 256, GEMM_SMEM>>>(p_wt_h + wo);

        gates2_kernel<<<NT/8, 256>>>(p_wc + (size_t)l*DI*16, bif + l*2*NH);
        gatescan_kernel<<<NBH, 256>>>();

        attn2_kernel<<<dim3(16, NBH), 256, ATTN2_SMEM>>>();

        gnmerge_kernel<<<NT, 512>>>(gn_g + l*DI, gn_b + l*DI, skip + l*DI);

        mmagemm2_kernel<0><<<dim3(NT/128, D/128), 256, GEMM_SMEM>>>(
            p_mix_h, p_mix_l, DI, p_wt_h + wo + WT_DN_OFF,
            bdown + l*D, p_h, p_h, D, nullptr, nullptr, 0, DI);
    }

    final_kernel<<<NB, 256>>>(lnf_g, lnf_b, Wf, bf, out);
}

// round 13
// speedup vs baseline: 1.0586x; 1.0207x over previous
#include <cuda_runtime.h>
#include <cuda_fp16.h>
#include <math.h>
#include <stdint.h>

#define D   256
#define DI  512
#define NH  4
#define DH  128
#define NL  4
#define KC  4
#define NB  8
#define SS  1024
#define NT  (NB*SS)
#define NBH (NB*NH)

// ---------------- scratch ----------------
__device__ float g_h [NT*D];
__device__ float g_up[NT*2*DI];
__device__ float g_xc[NT*DI];
__device__ float g_htp[2*NT*DI];
__device__ float g_rs [2*NBH*SS];
__device__ float g_gates[NT*2*NH];
__device__ float g_alpha[NBH*SS];
__device__ float g_beta [NBH*SS];
__device__ float g_m    [NBH*SS];
__device__ float g_wc   [NL*DI*16];

__device__ __half g_hn_h[NT*D],  g_hn_l[NT*D];
__device__ __half g_xc_h[NT*DI], g_xc_l[NT*DI];
__device__ __half g_xm_h[NT*DI], g_xm_l[NT*DI];
__device__ __half g_mix_h[NT*DI], g_mix_l[NT*DI];
__device__ __half g_qh[NT*DI], g_ql[NT*DI];
__device__ __half g_kh[NT*DI];
__device__ __half g_vh[NT*DI];

#define WT_UP_OFF   0
#define WT_Q_OFF    262144
#define WT_K_OFF    524288
#define WT_V_OFF    786432
#define WT_DN_OFF   1048576
#define WT_L        1179648
__device__ __half g_wt_h[NL*WT_L];

__device__ __forceinline__ uint32_t smem_u32(const void* p) {
    uint32_t a;
    asm("{ .reg .u64 t; cvta.to.shared.u64 t, %1; cvt.u32.u64 %0, t; }" : "=r"(a) : "l"(p));
    return a;
}
__device__ __forceinline__ void ldmx4(uint32_t* r, uint32_t addr) {
    asm volatile("ldmatrix.sync.aligned.m8n8.x4.shared.b16 {%0,%1,%2,%3}, [%4];"
        : "=r"(r[0]), "=r"(r[1]), "=r"(r[2]), "=r"(r[3]) : "r"(addr));
}
__device__ __forceinline__ void mma16816(float* d, const uint32_t* a, const uint32_t* b) {
    asm volatile(
        "mma.sync.aligned.m16n8k16.row.col.f32.f16.f16.f32 "
        "{%0,%1,%2,%3}, {%4,%5,%6,%7}, {%8,%9}, {%0,%1,%2,%3};"
        : "+f"(d[0]), "+f"(d[1]), "+f"(d[2]), "+f"(d[3])
        : "r"(a[0]), "r"(a[1]), "r"(a[2]), "r"(a[3]), "r"(b[0]), "r"(b[1]));
}
__device__ __forceinline__ uint32_t packh2(float lo, float hi) {
    __half2 p = __floats2half2_rn(lo, hi);
    return *(uint32_t*)&p;
}
__device__ __forceinline__ void cpa16(uint32_t s, const void* g) {
    asm volatile("cp.async.cg.shared.global [%0], [%1], 16;" :: "r"(s), "l"(g));
}
#define CP_COMMIT() asm volatile("cp.async.commit_group;" ::: "memory")
#define CP_WAIT0()  asm volatile("cp.async.wait_group 0;" ::: "memory")

// ---------------- embed ----------------
__global__ void embed_kernel(const float* __restrict__ x, const float* __restrict__ tf,
                             const float* __restrict__ Wp, const float* __restrict__ bp) {
    int t = blockIdx.x, d = threadIdx.x;
    float acc = bp[d] + x[t] * Wp[d];
#pragma unroll
    for (int j = 0; j < 4; j++) acc += tf[t*4 + j] * Wp[(1+j)*D + d];
    g_h[t*D + d] = acc;
}

// ---------------- LayerNorm D=256 -> fp16 hi/lo ----------------
__global__ void ln256_kernel(const float* __restrict__ in, const float* __restrict__ g,
                             const float* __restrict__ b) {
    int t = blockIdx.x, tid = threadIdx.x;
    __shared__ float red[256];
    float v = in[t*256 + tid];
    red[tid] = v; __syncthreads();
    for (int off = 128; off > 0; off >>= 1) { if (tid < off) red[tid] += red[tid+off]; __syncthreads(); }
    float mean = red[0] * (1.f/256.f); __syncthreads();
    float c = v - mean;
    red[tid] = c*c; __syncthreads();
    for (int off = 128; off > 0; off >>= 1) { if (tid < off) red[tid] += red[tid+off]; __syncthreads(); }
    float var = red[0] * (1.f/256.f);
    float y = c * rsqrtf(var + 1e-5f) * g[tid] + b[tid];
    __half h = __float2half_rn(y);
    g_hn_h[t*256 + tid] = h;
    g_hn_l[t*256 + tid] = __float2half_rn(y - __half2float(h));
}

// ---------------- batched weight transpose ----------------
__global__ void wsplit_all(const float* __restrict__ Wbase, long wstride, int K, int N,
                           __half* __restrict__ th, long ostride) {
    __shared__ float tile[32][33];
    int l = blockIdx.z;
    const float* W = Wbase + (size_t)l*wstride;
    __half* out = th + (size_t)l*ostride;
    int k0 = blockIdx.x*32, n0 = blockIdx.y*32;
    int tx = threadIdx.x, ty = threadIdx.y;
    for (int i = ty; i < 32; i += 8)
        tile[i][tx] = W[(size_t)(k0+i)*N + n0 + tx];
    __syncthreads();
    for (int i = ty; i < 32; i += 8)
        out[(size_t)(n0+i)*K + k0 + tx] = __float2half_rn(tile[tx][i]);
}

// ---------------- combined gate weights ----------------
__global__ void wcomb_kernel(const float* __restrict__ Wq0, const float* __restrict__ Wk0,
                             const float* __restrict__ Wv0, const float* __restrict__ Wif0,
                             float* __restrict__ wc0) {
    int i = blockIdx.x, l = blockIdx.y;
    const float* Wq = Wq0 + (size_t)l*DI*DI;
    const float* Wk = Wk0 + (size_t)l*DI*DI;
    const float* Wv = Wv0 + (size_t)l*DI*DI;
    const float* Wif = Wif0 + (size_t)l*3*DI*8;
    float* wc = wc0 + (size_t)l*DI*16;
    int warp = threadIdx.x >> 5, lane = threadIdx.x & 31;
    float a1 = 0.f, a2 = 0.f;
    for (int j = lane; j < DI; j += 32) {
        a1 += Wq[(size_t)i*DI + j] * Wif[j*8 + warp]
            + Wk[(size_t)i*DI + j] * Wif[(DI + j)*8 + warp];
        a2 += Wv[(size_t)i*DI + j] * Wif[(2*DI + j)*8 + warp];
    }
#pragma unroll
    for (int d = 16; d > 0; d >>= 1) {
        a1 += __shfl_xor_sync(0xFFFFFFFFu, a1, d);
        a2 += __shfl_xor_sync(0xFFFFFFFFu, a2, d);
    }
    if (lane == 0) {
        wc[i*16 + warp] = a1;
        wc[i*16 + 8 + warp] = a2;
    }
}

// ---------------- gates ----------------
__global__ void gates2_kernel(const float* __restrict__ wc, const float* __restrict__ bif) {
    int warp = threadIdx.x >> 5, lane = threadIdx.x & 31;
    int t = blockIdx.x*8 + warp;
    float acc[8];
#pragma unroll
    for (int g = 0; g < 8; g++) acc[g] = 0.f;
    const float* xcr = g_xc + (size_t)t*DI;
    const float* xmr = g_up + (size_t)t*2*DI;
    for (int j = lane; j < DI; j += 32) {
        float xcv = xcr[j], xmv = xmr[j];
        const float* w = wc + j*16;
#pragma unroll
        for (int g = 0; g < 8; g++) acc[g] += xcv*w[g] + xmv*w[8+g];
    }
#pragma unroll
    for (int g = 0; g < 8; g++) {
#pragma unroll
        for (int d = 16; d > 0; d >>= 1) acc[g] += __shfl_xor_sync(0xFFFFFFFFu, acc[g], d);
    }
    if (lane < 8) g_gates[(size_t)t*8 + lane] = acc[lane] + bif[lane];
}

// ================= shared GEMM machinery (128-row tiles) =================
#define TSTR 40
#define OFF_AH 0
#define OFF_AL 10240
#define OFF_BH 20480
#define STAGE_B 30720
#define GEMM_SMEM (2*STAGE_B)

struct GemmCtx {
    uint32_t aoff[2][2], boff[4][2];
    uint32_t soA, soB;
    int wm, wn, lane;
};
__device__ __forceinline__ void gemm_init(GemmCtx& c, int tid) {
    int warp = tid >> 5; c.lane = tid & 31;
    c.wm = warp >> 1; c.wn = warp & 1;
#pragma unroll
    for (int mt = 0; mt < 2; mt++)
#pragma unroll
        for (int ks = 0; ks < 2; ks++)
            c.aoff[mt][ks] = ((c.wm*32 + mt*16 + (c.lane & 15))*TSTR + ks*16 + ((c.lane >> 4) << 3))*2;
#pragma unroll
    for (int ntp = 0; ntp < 4; ntp++)
#pragma unroll
        for (int ks = 0; ks < 2; ks++)
            c.boff[ntp][ks] = ((c.wn*64 + ntp*16 + ((c.lane >> 4) << 3) + (c.lane & 7))*TSTR
                               + ks*16 + (((c.lane >> 3) & 1) << 3))*2;
    int ldRow = tid >> 2, ldQuad = tid & 3;
    c.soA = (ldRow*TSTR + ldQuad*8)*2;
    c.soB = ((ldRow+64)*TSTR + ldQuad*8)*2;
}
__device__ __forceinline__ void gemm_stage(const GemmCtx& c, uint32_t st, int tid,
                                           const __half* Ah0, const __half* Al0, int lda,
                                           const __half* Bh0, int K, int k0) {
    int ldRow = tid >> 2, ldQuad = tid & 3;
    cpa16(st + OFF_AH + c.soA, Ah0 + (size_t)ldRow*lda + k0 + ldQuad*8);
    cpa16(st + OFF_AL + c.soA, Al0 + (size_t)ldRow*lda + k0 + ldQuad*8);
    cpa16(st + OFF_BH + c.soA, Bh0 + (size_t)ldRow*K + k0 + ldQuad*8);
    cpa16(st + OFF_AH + c.soB, Ah0 + (size_t)(ldRow+64)*lda + k0 + ldQuad*8);
    cpa16(st + OFF_AL + c.soB, Al0 + (size_t)(ldRow+64)*lda + k0 + ldQuad*8);
    cpa16(st + OFF_BH + c.soB, Bh0 + (size_t)(ldRow+64)*K + k0 + ldQuad*8);
    CP_COMMIT();
}
__device__ __forceinline__ void gemm_math(const GemmCtx& c, uint32_t st, float acc[2][8][4]) {
    uint32_t sAh_b = st + OFF_AH, sAl_b = st + OFF_AL, sBh_b = st + OFF_BH;
#pragma unroll
    for (int ks = 0; ks < 2; ks++) {
        uint32_t ah[2][4], al[2][4], bh[4][4];
#pragma unroll
        for (int mt = 0; mt < 2; mt++) {
            ldmx4(ah[mt], sAh_b + c.aoff[mt][ks]);
            ldmx4(al[mt], sAl_b + c.aoff[mt][ks]);
        }
#pragma unroll
        for (int ntp = 0; ntp < 4; ntp++)
            ldmx4(bh[ntp], sBh_b + c.boff[ntp][ks]);
#pragma unroll
        for (int mt = 0; mt < 2; mt++)
#pragma unroll
            for (int nt = 0; nt < 8; nt++) {
                int p = nt >> 1, hh = (nt & 1) * 2;
                mma16816(acc[mt][nt], ah[mt], &bh[p][hh]);
                mma16816(acc[mt][nt], al[mt], &bh[p][hh]);
            }
    }
}

// MODE: 2 fp32 + hi/lo split for col<DI (up-GEMM)
template<int MODE>
__global__ void __launch_bounds__(256)
mmagemm2_kernel(const __half* __restrict__ Ah, const __half* __restrict__ Al, int lda,
                const __half* __restrict__ Bh,
                const float* __restrict__ bias, const float* __restrict__ resid,
                float* __restrict__ C, int ldc,
                __half* __restrict__ Ohi, __half* __restrict__ Olo, int ldo,
                int K) {
    extern __shared__ char dsm[];
    uint32_t sb = smem_u32(dsm);
    int tid = threadIdx.x;
    GemmCtx c; gemm_init(c, tid);
    int rowBase = blockIdx.x * 128;
    int colBase = blockIdx.y * 128;
    const __half* Ah0 = Ah + (size_t)rowBase*lda;
    const __half* Al0 = Al + (size_t)rowBase*lda;
    const __half* Bh0 = Bh + (size_t)colBase*K;

    float acc[2][8][4];
#pragma unroll
    for (int mt = 0; mt < 2; mt++)
#pragma unroll
        for (int nt = 0; nt < 8; nt++)
#pragma unroll
            for (int i = 0; i < 4; i++) acc[mt][nt][i] = 0.f;

    int nch = K >> 5;
    gemm_stage(c, sb, tid, Ah0, Al0, lda, Bh0, K, 0);
    int buf = 0;
    for (int ch = 0; ch < nch; ch++) {
        CP_WAIT0();
        __syncthreads();
        if (ch + 1 < nch)
            gemm_stage(c, sb + (buf^1)*STAGE_B, tid, Ah0, Al0, lda, Bh0, K, (ch+1) << 5);
        gemm_math(c, sb + buf*STAGE_B, acc);
        buf ^= 1;
        __syncthreads();
    }

    int r0b = rowBase + c.wm*32 + (c.lane >> 2);
    int cb  = colBase + c.wn*64 + (c.lane & 3)*2;
#pragma unroll
    for (int mt = 0; mt < 2; mt++) {
#pragma unroll
        for (int nt = 0; nt < 8; nt++) {
            int col = cb + nt*8;
#pragma unroll
            for (int half = 0; half < 2; half++) {
                int row = r0b + mt*16 + half*8;
                float vx = acc[mt][nt][half*2+0];
                float vy = acc[mt][nt][half*2+1];
                if (bias) { vx += bias[col]; vy += bias[col+1]; }
                if (MODE == 0 && resid) {
                    const float2 r2 = *(const float2*)(resid + (size_t)row*ldc + col);
                    vx += r2.x; vy += r2.y;
                }
                float2 o; o.x = vx; o.y = vy;
                *(float2*)(C + (size_t)row*ldc + col) = o;
                if (MODE == 2 && col < DI) {
                    __half hx = __float2half_rn(vx);
                    __half hy = __float2half_rn(vy);
                    __half2 hv; hv.x = hx; hv.y = hy;
                    __half2 lv;
                    lv.x = __float2half_rn(vx - __half2float(hx));
                    lv.y = __float2half_rn(vy - __half2float(hy));
                    *(__half2*)(Ohi + (size_t)row*ldo + col) = hv;
                    *(__half2*)(Olo + (size_t)row*ldo + col) = lv;
                }
            }
        }
    }
}

// ---------------- down-GEMM: 64x128 tiles for occupancy ----------------
#define D64_AH 0
#define D64_AL 5120
#define D64_BH 10240
#define D64_STAGE 20480
#define D64_SMEM (2*D64_STAGE)

__global__ void __launch_bounds__(256)
dngemm_kernel(const __half* __restrict__ Ah, const __half* __restrict__ Al,
              const __half* __restrict__ Bh, const float* __restrict__ bias,
              float* __restrict__ C) {
    extern __shared__ char dsm[];
    uint32_t sb = smem_u32(dsm);
    int tid = threadIdx.x;
    int warp = tid >> 5, lane = tid & 31;
    int wm = warp >> 1, wn = warp & 1;      // wm 0..3 (16 rows each), wn 0..1 (64 cols)
    int rowBase = blockIdx.x * 64;
    int colBase = blockIdx.y * 128;
    const __half* Ah0 = Ah + (size_t)rowBase*DI;
    const __half* Al0 = Al + (size_t)rowBase*DI;
    const __half* Bh0 = Bh + (size_t)colBase*DI;

    float acc[8][4];
#pragma unroll
    for (int nt = 0; nt < 8; nt++)
#pragma unroll
        for (int i = 0; i < 4; i++) acc[nt][i] = 0.f;

    uint32_t aoff[2], boff[4][2];
#pragma unroll
    for (int ks = 0; ks < 2; ks++)
        aoff[ks] = ((wm*16 + (lane & 15))*TSTR + ks*16 + ((lane >> 4) << 3))*2;
#pragma unroll
    for (int ntp = 0; ntp < 4; ntp++)
#pragma unroll
        for (int ks = 0; ks < 2; ks++)
            boff[ntp][ks] = ((wn*64 + ntp*16 + ((lane >> 4) << 3) + (lane & 7))*TSTR
                             + ks*16 + (((lane >> 3) & 1) << 3))*2;

    int arow = tid >> 2, aq = tid & 3;
    uint32_t soA = (arow*TSTR + aq*8)*2;
    int brow = tid >> 1, bq = (tid & 1)*2;
    uint32_t soB0 = (brow*TSTR + bq*8)*2;
    uint32_t soB1 = (brow*TSTR + (bq+1)*8)*2;

    // prefetch chunk 0
    {
        uint32_t st = sb;
        cpa16(st + D64_AH + soA, Ah0 + (size_t)arow*DI + aq*8);
        cpa16(st + D64_AL + soA, Al0 + (size_t)arow*DI + aq*8);
        cpa16(st + D64_BH + soB0, Bh0 + (size_t)brow*DI + bq*8);
        cpa16(st + D64_BH + soB1, Bh0 + (size_t)brow*DI + (bq+1)*8);
        CP_COMMIT();
    }
    int buf = 0;
    for (int ch = 0; ch < 16; ch++) {
        CP_WAIT0();
        __syncthreads();
        if (ch + 1 < 16) {
            int k1 = (ch + 1) << 5;
            uint32_t st = sb + (buf^1)*D64_STAGE;
            cpa16(st + D64_AH + soA, Ah0 + (size_t)arow*DI + k1 + aq*8);
            cpa16(st + D64_AL + soA, Al0 + (size_t)arow*DI + k1 + aq*8);
            cpa16(st + D64_BH + soB0, Bh0 + (size_t)brow*DI + k1 + bq*8);
            cpa16(st + D64_BH + soB1, Bh0 + (size_t)brow*DI + k1 + (bq+1)*8);
            CP_COMMIT();
        }
        uint32_t st = sb + buf*D64_STAGE;
#pragma unroll
        for (int ks = 0; ks < 2; ks++) {
            uint32_t ah[4], al[4], bh[4][4];
            ldmx4(ah, st + D64_AH + aoff[ks]);
            ldmx4(al, st + D64_AL + aoff[ks]);
#pragma unroll
            for (int ntp = 0; ntp < 4; ntp++)
                ldmx4(bh[ntp], st + D64_BH + boff[ntp][ks]);
#pragma unroll
            for (int nt = 0; nt < 8; nt++) {
                int p = nt >> 1, hh = (nt & 1) * 2;
                mma16816(acc[nt], ah, &bh[p][hh]);
                mma16816(acc[nt], al, &bh[p][hh]);
            }
        }
        buf ^= 1;
        __syncthreads();
    }

    int r0b = rowBase + wm*16 + (lane >> 2);
    int cb  = colBase + wn*64 + (lane & 3)*2;
#pragma unroll
    for (int nt = 0; nt < 8; nt++) {
        int col = cb + nt*8;
#pragma unroll
        for (int half = 0; half < 2; half++) {
            int row = r0b + half*8;
            float vx = acc[nt][half*2+0] + bias[col];
            float vy = acc[nt][half*2+1] + bias[col+1];
            float2 r2 = *(const float2*)(C + (size_t)row*D + col);
            vx += r2.x; vy += r2.y;
            float2 o; o.x = vx; o.y = vy;
            *(float2*)(C + (size_t)row*D + col) = o;
        }
    }
}

// ---------------- fused Q/K/V GEMM ----------------
__global__ void __launch_bounds__(256)
qkvgemm_kernel(const __half* __restrict__ wt) {
    extern __shared__ char dsm[];
    uint32_t sb = smem_u32(dsm);
    int tid = threadIdx.x;
    GemmCtx c; gemm_init(c, tid);
    int rowBase = blockIdx.x * 128;
    int yb = blockIdx.y;
    int sel = yb >> 2;
    int colBase = (yb & 3) * 128;

    const __half* Ah = (sel == 2) ? g_xm_h : g_xc_h;
    const __half* Al = (sel == 2) ? g_xm_l : g_xc_l;
    const __half* Bh0 = wt + (sel == 0 ? WT_Q_OFF : sel == 1 ? WT_K_OFF : WT_V_OFF)
                      + (size_t)colBase*DI;
    const __half* Ah0 = Ah + (size_t)rowBase*DI;
    const __half* Al0 = Al + (size_t)rowBase*DI;

    float acc[2][8][4];
#pragma unroll
    for (int mt = 0; mt < 2; mt++)
#pragma unroll
        for (int nt = 0; nt < 8; nt++)
#pragma unroll
            for (int i = 0; i < 4; i++) acc[mt][nt][i] = 0.f;

    gemm_stage(c, sb, tid, Ah0, Al0, DI, Bh0, DI, 0);
    int buf = 0;
    for (int ch = 0; ch < 16; ch++) {
        CP_WAIT0();
        __syncthreads();
        if (ch + 1 < 16)
            gemm_stage(c, sb + (buf^1)*STAGE_B, tid, Ah0, Al0, DI, Bh0, DI, (ch+1) << 5);
        gemm_math(c, sb + buf*STAGE_B, acc);
        buf ^= 1;
        __syncthreads();
    }

    __half* Ohi = (sel == 0) ? g_qh : (sel == 1) ? g_kh : g_vh;
    int r0b = rowBase + c.wm*32 + (c.lane >> 2);
    int cb  = colBase + c.wn*64 + (c.lane & 3)*2;
#pragma unroll
    for (int mt = 0; mt < 2; mt++) {
#pragma unroll
        for (int nt = 0; nt < 8; nt++) {
            int col = cb + nt*8;
#pragma unroll
            for (int half = 0; half < 2; half++) {
                int row = r0b + mt*16 + half*8;
                float vx = acc[mt][nt][half*2+0];
                float vy = acc[mt][nt][half*2+1];
                __half hx = __float2half_rn(vx);
                __half hy = __float2half_rn(vy);
                __half2 hv; hv.x = hx; hv.y = hy;
                *(__half2*)(Ohi + (size_t)row*DI + col) = hv;
                if (sel == 0) {
                    __half2 lv;
                    lv.x = __float2half_rn(vx - __half2float(hx));
                    lv.y = __float2half_rn(vy - __half2float(hy));
                    *(__half2*)(g_ql + (size_t)row*DI + col) = lv;
                }
            }
        }
    }
}

// ---------------- conv + SiLU ----------------
__global__ void conv_kernel(const float* __restrict__ w, const float* __restrict__ bias) {
    int idx = blockIdx.x * blockDim.x + threadIdx.x;
    int c = idx % DI;
    int t = idx / DI;
    int s = t % SS;
    float acc = bias[c];
#pragma unroll
    for (int j = 0; j < KC; j++) {
        int ss = s - 3 + j;
        if (ss >= 0) acc += g_up[(size_t)(t - 3 + j)*2*DI + c] * w[j*DI + c];
    }
    float y = acc / (1.f + __expf(-acc));
    g_xc[idx] = y;
    __half h = __float2half_rn(y);
    g_xc_h[idx] = h;
    g_xc_l[idx] = __float2half_rn(y - __half2float(h));
}

// ---------------- gate scan: smem preload + warp scan ----------------
__global__ void __launch_bounds__(256) gatescan_kernel() {
    __shared__ float sif[SS], sff[SS];
    int bh = blockIdx.x;
    int b = bh >> 2, h = bh & 3;
    int tid = threadIdx.x;
    for (int i = tid; i < SS; i += 256) {
        const float* gp = g_gates + (size_t)(b*SS + i)*8;
        sif[i] = gp[h];
        sff[i] = gp[NH + h];
    }
    __syncthreads();
    if (tid < 32) {
        int lane = tid;
        float carryF = 0.f, carryM = -1e30f;
        for (int c = 0; c < SS/32; c++) {
            int t = c*32 + lane;
            float fp = sff[t], ipv = sif[t];
            float lf = (fp >= 0.f) ? -log1pf(__expf(-fp)) : fp - log1pf(__expf(fp));
            float s = lf;
#pragma unroll
            for (int d = 1; d < 32; d <<= 1) {
                float v = __shfl_up_sync(0xFFFFFFFFu, s, d);
                if (lane >= d) s += v;
            }
            float Fc = carryF + s;
            float bt = ipv - Fc;
            float mx = bt;
#pragma unroll
            for (int d = 1; d < 32; d <<= 1) {
                float v = __shfl_up_sync(0xFFFFFFFFu, mx, d);
                if (lane >= d) mx = fmaxf(mx, v);
            }
            float rmax = fmaxf(carryM, mx);
            g_beta [bh*SS + t] = bt;
            g_alpha[bh*SS + t] = -rmax;
            g_m    [bh*SS + t] = Fc + rmax;
            carryF += __shfl_sync(0xFFFFFFFFu, s, 31);
            carryM  = fmaxf(carryM, __shfl_sync(0xFFFFFFFFu, rmax, 31));
        }
    }
}

// ================= split-s fp16 attention, heavy-first, AV hi-only =================
#define STRQ 136
#define STRV 40
#define A2_QH 0
#define A2_QL (A2_QH + 128*STRQ*2)
#define A2_KH (A2_QL + 128*STRQ*2)
#define A2_VH (A2_KH + 32*STRQ*2)
#define A2_BT (A2_VH + 128*STRV*2)
#define ATTN2_SMEM (A2_BT + 32*4)
#define SCALE 0.08838834764831845f

__global__ void __launch_bounds__(256) attn2_kernel() {
    extern __shared__ char sm2[];
    __half* Qh = (__half*)(sm2 + A2_QH);
    __half* Ql = (__half*)(sm2 + A2_QL);
    __half* Kh = (__half*)(sm2 + A2_KH);
    __half* Vh = (__half*)(sm2 + A2_VH);
    float* bts = (float*)(sm2 + A2_BT);

    int xw = blockIdx.x;
    int qt = 7 - (xw >> 1);
    int sh = xw & 1;
    int bh = blockIdx.y;
    int b = bh >> 2, h = bh & 3;
    int tid = threadIdx.x, warp = tid >> 5, lane = tid & 31;
    int t0 = qt * 128;

#pragma unroll
    for (int j = 0; j < 8; j++) {
        int i = tid + j*256;
        int row = i >> 4, c8 = (i & 15)*8;
        size_t gb = (size_t)(b*SS + t0 + row)*DI + h*DH + c8;
        *(uint4*)(Qh + row*STRQ + c8) = *(const uint4*)(g_qh + gb);
        *(uint4*)(Ql + row*STRQ + c8) = *(const uint4*)(g_ql + gb);
    }

    int tr0 = t0 + warp*16 + (lane >> 2);
    int tr1 = tr0 + 8;
    float al0 = g_alpha[bh*SS + tr0];
    float al1 = g_alpha[bh*SS + tr1];

    float O[16][4];
#pragma unroll
    for (int nt = 0; nt < 16; nt++)
#pragma unroll
        for (int i = 0; i < 4; i++) O[nt][i] = 0.f;
    float rs0 = 0.f, rs1 = 0.f;

    uint32_t sQh = smem_u32(Qh), sQl = smem_u32(Ql);
    uint32_t sKh = smem_u32(Kh), sVh = smem_u32(Vh);

    uint32_t qoff[8], koff[2][8], voff[8][2];
#pragma unroll
    for (int ks = 0; ks < 8; ks++)
        qoff[ks] = ((warp*16 + (lane & 15))*STRQ + ks*16 + ((lane >> 4) << 3))*2;
#pragma unroll
    for (int np = 0; np < 2; np++)
#pragma unroll
        for (int ks = 0; ks < 8; ks++)
            koff[np][ks] = ((np*16 + ((lane >> 4) << 3) + (lane & 7))*STRQ
                            + ks*16 + (((lane >> 3) & 1) << 3))*2;
#pragma unroll
    for (int np = 0; np < 8; np++)
#pragma unroll
        for (int kv = 0; kv < 2; kv++)
            voff[np][kv] = ((np*16 + ((lane >> 4) << 3) + (lane & 7))*STRV
                            + kv*16 + (((lane >> 3) & 1) << 3))*2;

    int half_tiles = 2*(qt + 1);
    int st_lo = sh * half_tiles;
    int st_hi = st_lo + half_tiles;
    for (int st = st_lo; st < st_hi; st++) {
        int s0 = st * 32;
        __syncthreads();
#pragma unroll
        for (int j = 0; j < 2; j++) {
            int i = tid + j*256;
            int row = i >> 4, c8 = (i & 15)*8;
            size_t gb = (size_t)(b*SS + s0 + row)*DI + h*DH + c8;
            *(uint4*)(Kh + row*STRQ + c8) = *(const uint4*)(g_kh + gb);
            uint4 vh4 = *(const uint4*)(g_vh + gb);
            const __half* vhp = (const __half*)&vh4;
#pragma unroll
            for (int e = 0; e < 8; e++)
                Vh[(c8+e)*STRV + row] = vhp[e];
        }
        if (tid < 32) bts[tid] = g_beta[bh*SS + s0 + tid];
        __syncthreads();

        float S[4][4];
#pragma unroll
        for (int nt = 0; nt < 4; nt++)
#pragma unroll
            for (int i = 0; i < 4; i++) S[nt][i] = 0.f;
#pragma unroll
        for (int ks = 0; ks < 8; ks++) {
            uint32_t ah[4], al[4], bkh[2][4];
            ldmx4(ah, sQh + qoff[ks]);
            ldmx4(al, sQl + qoff[ks]);
            ldmx4(bkh[0], sKh + koff[0][ks]);
            ldmx4(bkh[1], sKh + koff[1][ks]);
#pragma unroll
            for (int nt = 0; nt < 4; nt++) {
                int p = nt >> 1, hh = (nt & 1)*2;
                mma16816(S[nt], ah, &bkh[p][hh]);
                mma16816(S[nt], al, &bkh[p][hh]);
            }
        }

        uint32_t Ph[2][4];
#pragma unroll
        for (int nt = 0; nt < 4; nt++) {
            float pv[4];
#pragma unroll
            for (int r = 0; r < 4; r++) {
                int trow = (r < 2) ? tr0 : tr1;
                float alv = (r < 2) ? al0 : al1;
                int cl = nt*8 + (lane & 3)*2 + (r & 1);
                int sc = s0 + cl;
                float w = (sc <= trow) ? __expf(alv + bts[cl]) : 0.f;
                float p = S[nt][r] * SCALE * w;
                if (r < 2) rs0 += p; else rs1 += p;
                pv[r] = p;
            }
            int kv = nt >> 1;
            if ((nt & 1) == 0) {
                Ph[kv][0] = packh2(pv[0], pv[1]);
                Ph[kv][1] = packh2(pv[2], pv[3]);
            } else {
                Ph[kv][2] = packh2(pv[0], pv[1]);
                Ph[kv][3] = packh2(pv[2], pv[3]);
            }
        }

#pragma unroll
        for (int kv = 0; kv < 2; kv++) {
#pragma unroll
            for (int np = 0; np < 8; np++) {
                uint32_t bvh[4];
                ldmx4(bvh, sVh + voff[np][kv]);
#pragma unroll
                for (int hh = 0; hh < 2; hh++)
                    mma16816(O[np*2 + hh], Ph[kv], &bvh[hh*2]);
            }
        }
    }

    rs0 += __shfl_xor_sync(0xFFFFFFFFu, rs0, 1);
    rs0 += __shfl_xor_sync(0xFFFFFFFFu, rs0, 2);
    rs1 += __shfl_xor_sync(0xFFFFFFFFu, rs1, 1);
    rs1 += __shfl_xor_sync(0xFFFFFFFFu, rs1, 2);
    if ((lane & 3) == 0) {
        g_rs[sh*NBH*SS + bh*SS + tr0] = rs0;
        g_rs[sh*NBH*SS + bh*SS + tr1] = rs1;
    }

    float* o0 = g_htp + (size_t)sh*NT*DI + (size_t)(b*SS + tr0)*DI + h*DH + (lane & 3)*2;
    float* o1 = g_htp + (size_t)sh*NT*DI + (size_t)(b*SS + tr1)*DI + h*DH + (lane & 3)*2;
#pragma unroll
    for (int nt = 0; nt < 16; nt++) {
        float2 v0; v0.x = O[nt][0]; v0.y = O[nt][1];
        float2 v1; v1.x = O[nt][2]; v1.y = O[nt][3];
        *(float2*)(o0 + nt*8) = v0;
        *(float2*)(o1 + nt*8) = v1;
    }
}

// ---------------- combine partials + per-head LN + skip + SiLU gate ----------------
__global__ void gnmerge_kernel(const float* __restrict__ gn_g, const float* __restrict__ gn_b,
                               const float* __restrict__ skip) {
    int t = blockIdx.x, tid = threadIdx.x;
    __shared__ float red[512];
    int l = tid & 127;
    int gbase = (tid >> 7) << 7;
    int b = t >> 10, s = t & 1023;
    int h = tid >> 7;
    int bh = b*NH + h;
    float rs = g_rs[bh*SS + s] + g_rs[NBH*SS + bh*SS + s];
    float me = __expf(-g_m[bh*SS + s]);
    float inv = 1.f / (fmaxf(fabsf(rs), me) + 1e-6f);
    float v = (g_htp[(size_t)t*DI + tid] + g_htp[(size_t)NT*DI + (size_t)t*DI + tid]) * inv;
    red[tid] = v; __syncthreads();
    for (int off = 64; off > 0; off >>= 1) { if (l < off) red[tid] += red[tid+off]; __syncthreads(); }
    float mean = red[gbase] * (1.f/128.f); __syncthreads();
    float c = v - mean;
    red[tid] = c*c; __syncthreads();
    for (int off = 64; off > 0; off >>= 1) { if (l < off) red[tid] += red[tid+off]; __syncthreads(); }
    float var = red[gbase] * (1.f/128.f);
    float y = c * rsqrtf(var + 1e-5f) * gn_g[tid] + gn_b[tid];
    y += skip[tid] * g_xc[(size_t)t*DI + tid];
    float z = g_up[(size_t)t*2*DI + DI + tid];
    y *= z / (1.f + __expf(-z));
    __half hh = __float2half_rn(y);
    g_mix_h[(size_t)t*DI + tid] = hh;
    g_mix_l[(size_t)t*DI + tid] = __float2half_rn(y - __half2float(hh));
}

// ---------------- final LN + projection ----------------
__global__ void final_kernel(const float* __restrict__ lnf_g, const float* __restrict__ lnf_b,
                             const float* __restrict__ Wf, const float* __restrict__ bf,
                             float* __restrict__ out) {
    int b = blockIdx.x, tid = threadIdx.x;
    __shared__ float red[256];
    float v = g_h[(size_t)(b*SS + SS - 1)*D + tid];
    red[tid] = v; __syncthreads();
    for (int off = 128; off > 0; off >>= 1) { if (tid < off) red[tid] += red[tid+off]; __syncthreads(); }
    float mean = red[0] * (1.f/256.f); __syncthreads();
    float c = v - mean;
    red[tid] = c*c; __syncthreads();
    for (int off = 128; off > 0; off >>= 1) { if (tid < off) red[tid] += red[tid+off]; __syncthreads(); }
    float var = red[0] * (1.f/256.f); __syncthreads();
    float y = c * rsqrtf(var + 1e-5f) * lnf_g[tid] + lnf_b[tid];
    red[tid] = y * Wf[tid]; __syncthreads();
    for (int off = 128; off > 0; off >>= 1) { if (tid < off) red[tid] += red[tid+off]; __syncthreads(); }
    if (tid == 0) out[b] = red[0] + bf[0];
}

// ---------------- host ----------------
static float* symaddrf(const void* sym) {
    void* p = nullptr;
    cudaGetSymbolAddress(&p, sym);
    return (float*)p;
}
static __half* symaddrh(const void* sym) {
    void* p = nullptr;
    cudaGetSymbolAddress(&p, sym);
    return (__half*)p;
}

extern "C" void kernel_launch(void* const* d_in, const int* in_sizes, int n_in,
                              void* d_out, int out_size) {
    const float* x      = (const float*)d_in[0];
    const float* tf     = (const float*)d_in[1];
    const float* Wp     = (const float*)d_in[2];
    const float* bp     = (const float*)d_in[3];
    const float* ln_g   = (const float*)d_in[4];
    const float* ln_b   = (const float*)d_in[5];
    const float* Wup    = (const float*)d_in[6];
    const float* bup    = (const float*)d_in[7];
    const float* conv_w = (const float*)d_in[8];
    const float* conv_b = (const float*)d_in[9];
    const float* Wq     = (const float*)d_in[10];
    const float* Wk     = (const float*)d_in[11];
    const float* Wv     = (const float*)d_in[12];
    const float* Wif    = (const float*)d_in[13];
    const float* bif    = (const float*)d_in[14];
    const float* gn_g   = (const float*)d_in[15];
    const float* gn_b   = (const float*)d_in[16];
    const float* skip   = (const float*)d_in[17];
    const float* Wdown  = (const float*)d_in[18];
    const float* bdown  = (const float*)d_in[19];
    const float* lnf_g  = (const float*)d_in[20];
    const float* lnf_b  = (const float*)d_in[21];
    const float* Wf     = (const float*)d_in[22];
    const float* bf     = (const float*)d_in[23];
    float* out = (float*)d_out;

    float* p_h   = symaddrf(g_h);
    float* p_up  = symaddrf(g_up);
    float* p_wc  = symaddrf(g_wc);
    __half* p_hn_h = symaddrh(g_hn_h);
    __half* p_hn_l = symaddrh(g_hn_l);
    __half* p_xm_h = symaddrh(g_xm_h);
    __half* p_xm_l = symaddrh(g_xm_l);
    __half* p_mix_h = symaddrh(g_mix_h);
    __half* p_mix_l = symaddrh(g_mix_l);
    __half* p_wt_h = symaddrh(g_wt_h);

    cudaFuncSetAttribute(attn2_kernel, cudaFuncAttributeMaxDynamicSharedMemorySize, ATTN2_SMEM);
    cudaFuncSetAttribute(mmagemm2_kernel<2>, cudaFuncAttributeMaxDynamicSharedMemorySize, GEMM_SMEM);
    cudaFuncSetAttribute(qkvgemm_kernel, cudaFuncAttributeMaxDynamicSharedMemorySize, GEMM_SMEM);
    cudaFuncSetAttribute(dngemm_kernel, cudaFuncAttributeMaxDynamicSharedMemorySize, D64_SMEM);

    dim3 wblk(32, 8);
    wsplit_all<<<dim3(D/32, 2*DI/32, NL), wblk>>>(Wup, (long)D*2*DI, D, 2*DI,
                                                  p_wt_h + WT_UP_OFF, WT_L);
    wsplit_all<<<dim3(DI/32, DI/32, NL), wblk>>>(Wq, (long)DI*DI, DI, DI,
                                                 p_wt_h + WT_Q_OFF, WT_L);
    wsplit_all<<<dim3(DI/32, DI/32, NL), wblk>>>(Wk, (long)DI*DI, DI, DI,
                                                 p_wt_h + WT_K_OFF, WT_L);
    wsplit_all<<<dim3(DI/32, DI/32, NL), wblk>>>(Wv, (long)DI*DI, DI, DI,
                                                 p_wt_h + WT_V_OFF, WT_L);
    wsplit_all<<<dim3(DI/32, D/32, NL), wblk>>>(Wdown, (long)DI*D, DI, D,
                                                p_wt_h + WT_DN_OFF, WT_L);
    wcomb_kernel<<<dim3(DI, NL), 256>>>(Wq, Wk, Wv, Wif, p_wc);

    embed_kernel<<<NT, 256>>>(x, tf, Wp, bp);

    for (int l = 0; l < NL; l++) {
        size_t wo = (size_t)l * WT_L;
        ln256_kernel<<<NT, 256>>>(p_h, ln_g + l*D, ln_b + l*D);

        mmagemm2_kernel<2><<<dim3(NT/128, 1024/128), 256, GEMM_SMEM>>>(
            p_hn_h, p_hn_l, D, p_wt_h + wo + WT_UP_OFF,
            bup + l*2*DI, nullptr, p_up, 2*DI, p_xm_h, p_xm_l, DI, D);

        conv_kernel<<<NT*DI/256, 256>>>(conv_w + l*KC*DI, conv_b + l*DI);

        qkvgemm_kernel<<<dim3(NT/128, 12), 256, GEMM_SMEM>>>(p_wt_h + wo);

        gates2_kernel<<<NT/8, 256>>>(p_wc + (size_t)l*DI*16, bif + l*2*NH);
        gatescan_kernel<<<NBH, 256>>>();

        attn2_kernel<<<dim3(16, NBH), 256, ATTN2_SMEM>>>();

        gnmerge_kernel<<<NT, 512>>>(gn_g + l*DI, gn_b + l*DI, skip + l*DI);

        dngemm_kernel<<<dim3(NT/64, D/128), 256, D64_SMEM>>>(
            p_mix_h, p_mix_l, p_wt_h + wo + WT_DN_OFF, bdown + l*D, p_h);
    }

    final_kernel<<<NB, 256>>>(lnf_g, lnf_b, Wf, bf, out);
}

// round 14
// speedup vs baseline: 1.1005x; 1.0396x over previous
#include <cuda_runtime.h>
#include <cuda_fp16.h>
#include <math.h>
#include <stdint.h>

#define D   256
#define DI  512
#define NH  4
#define DH  128
#define NL  4
#define KC  4
#define NB  8
#define SS  1024
#define NT  (NB*SS)
#define NBH (NB*NH)

// ---------------- scratch ----------------
__device__ float g_h [NT*D];
__device__ float g_up[NT*2*DI];
__device__ float g_xc[NT*DI];
__device__ float g_htp[2*NT*DI];
__device__ float g_rs [2*NBH*SS];
__device__ float g_gates[NT*2*NH];
__device__ float g_alpha[NBH*SS];
__device__ float g_beta [NBH*SS];
__device__ float g_m    [NBH*SS];
__device__ float g_wc   [NL*DI*16];

__device__ __half g_hn_h[NT*D],  g_hn_l[NT*D];
__device__ __half g_xc_h[NT*DI], g_xc_l[NT*DI];
__device__ __half g_xm_h[NT*DI], g_xm_l[NT*DI];
__device__ __half g_mix_h[NT*DI], g_mix_l[NT*DI];
__device__ __half g_qh[NT*DI];
__device__ __half g_kh[NT*DI];
__device__ __half g_vh[NT*DI];

#define WT_UP_OFF   0
#define WT_Q_OFF    262144
#define WT_K_OFF    524288
#define WT_V_OFF    786432
#define WT_DN_OFF   1048576
#define WT_L        1179648
__device__ __half g_wt_h[NL*WT_L];

__device__ __forceinline__ uint32_t smem_u32(const void* p) {
    uint32_t a;
    asm("{ .reg .u64 t; cvta.to.shared.u64 t, %1; cvt.u32.u64 %0, t; }" : "=r"(a) : "l"(p));
    return a;
}
__device__ __forceinline__ void ldmx4(uint32_t* r, uint32_t addr) {
    asm volatile("ldmatrix.sync.aligned.m8n8.x4.shared.b16 {%0,%1,%2,%3}, [%4];"
        : "=r"(r[0]), "=r"(r[1]), "=r"(r[2]), "=r"(r[3]) : "r"(addr));
}
__device__ __forceinline__ void mma16816(float* d, const uint32_t* a, const uint32_t* b) {
    asm volatile(
        "mma.sync.aligned.m16n8k16.row.col.f32.f16.f16.f32 "
        "{%0,%1,%2,%3}, {%4,%5,%6,%7}, {%8,%9}, {%0,%1,%2,%3};"
        : "+f"(d[0]), "+f"(d[1]), "+f"(d[2]), "+f"(d[3])
        : "r"(a[0]), "r"(a[1]), "r"(a[2]), "r"(a[3]), "r"(b[0]), "r"(b[1]));
}
__device__ __forceinline__ uint32_t packh2(float lo, float hi) {
    __half2 p = __floats2half2_rn(lo, hi);
    return *(uint32_t*)&p;
}
__device__ __forceinline__ void cpa16(uint32_t s, const void* g) {
    asm volatile("cp.async.cg.shared.global [%0], [%1], 16;" :: "r"(s), "l"(g));
}
#define CP_COMMIT() asm volatile("cp.async.commit_group;" ::: "memory")
#define CP_WAIT0()  asm volatile("cp.async.wait_group 0;" ::: "memory")

// ---------------- embed ----------------
__global__ void embed_kernel(const float* __restrict__ x, const float* __restrict__ tf,
                             const float* __restrict__ Wp, const float* __restrict__ bp) {
    int t = blockIdx.x, d = threadIdx.x;
    float acc = bp[d] + x[t] * Wp[d];
#pragma unroll
    for (int j = 0; j < 4; j++) acc += tf[t*4 + j] * Wp[(1+j)*D + d];
    g_h[t*D + d] = acc;
}

// ---------------- LayerNorm D=256 -> fp16 hi/lo ----------------
__global__ void ln256_kernel(const float* __restrict__ in, const float* __restrict__ g,
                             const float* __restrict__ b) {
    int t = blockIdx.x, tid = threadIdx.x;
    __shared__ float red[256];
    float v = in[t*256 + tid];
    red[tid] = v; __syncthreads();
    for (int off = 128; off > 0; off >>= 1) { if (tid < off) red[tid] += red[tid+off]; __syncthreads(); }
    float mean = red[0] * (1.f/256.f); __syncthreads();
    float c = v - mean;
    red[tid] = c*c; __syncthreads();
    for (int off = 128; off > 0; off >>= 1) { if (tid < off) red[tid] += red[tid+off]; __syncthreads(); }
    float var = red[0] * (1.f/256.f);
    float y = c * rsqrtf(var + 1e-5f) * g[tid] + b[tid];
    __half h = __float2half_rn(y);
    g_hn_h[t*256 + tid] = h;
    g_hn_l[t*256 + tid] = __float2half_rn(y - __half2float(h));
}

// ---------------- batched weight transpose ----------------
__global__ void wsplit_all(const float* __restrict__ Wbase, long wstride, int K, int N,
                           __half* __restrict__ th, long ostride) {
    __shared__ float tile[32][33];
    int l = blockIdx.z;
    const float* W = Wbase + (size_t)l*wstride;
    __half* out = th + (size_t)l*ostride;
    int k0 = blockIdx.x*32, n0 = blockIdx.y*32;
    int tx = threadIdx.x, ty = threadIdx.y;
    for (int i = ty; i < 32; i += 8)
        tile[i][tx] = W[(size_t)(k0+i)*N + n0 + tx];
    __syncthreads();
    for (int i = ty; i < 32; i += 8)
        out[(size_t)(n0+i)*K + k0 + tx] = __float2half_rn(tile[tx][i]);
}

// ---------------- combined gate weights ----------------
__global__ void wcomb_kernel(const float* __restrict__ Wq0, const float* __restrict__ Wk0,
                             const float* __restrict__ Wv0, const float* __restrict__ Wif0,
                             float* __restrict__ wc0) {
    int i = blockIdx.x, l = blockIdx.y;
    const float* Wq = Wq0 + (size_t)l*DI*DI;
    const float* Wk = Wk0 + (size_t)l*DI*DI;
    const float* Wv = Wv0 + (size_t)l*DI*DI;
    const float* Wif = Wif0 + (size_t)l*3*DI*8;
    float* wc = wc0 + (size_t)l*DI*16;
    int warp = threadIdx.x >> 5, lane = threadIdx.x & 31;
    float a1 = 0.f, a2 = 0.f;
    for (int j = lane; j < DI; j += 32) {
        a1 += Wq[(size_t)i*DI + j] * Wif[j*8 + warp]
            + Wk[(size_t)i*DI + j] * Wif[(DI + j)*8 + warp];
        a2 += Wv[(size_t)i*DI + j] * Wif[(2*DI + j)*8 + warp];
    }
#pragma unroll
    for (int d = 16; d > 0; d >>= 1) {
        a1 += __shfl_xor_sync(0xFFFFFFFFu, a1, d);
        a2 += __shfl_xor_sync(0xFFFFFFFFu, a2, d);
    }
    if (lane == 0) {
        wc[i*16 + warp] = a1;
        wc[i*16 + 8 + warp] = a2;
    }
}

// ---------------- gates ----------------
__global__ void gates2_kernel(const float* __restrict__ wc, const float* __restrict__ bif) {
    int warp = threadIdx.x >> 5, lane = threadIdx.x & 31;
    int t = blockIdx.x*8 + warp;
    float acc[8];
#pragma unroll
    for (int g = 0; g < 8; g++) acc[g] = 0.f;
    const float* xcr = g_xc + (size_t)t*DI;
    const float* xmr = g_up + (size_t)t*2*DI;
    for (int j = lane; j < DI; j += 32) {
        float xcv = xcr[j], xmv = xmr[j];
        const float* w = wc + j*16;
#pragma unroll
        for (int g = 0; g < 8; g++) acc[g] += xcv*w[g] + xmv*w[8+g];
    }
#pragma unroll
    for (int g = 0; g < 8; g++) {
#pragma unroll
        for (int d = 16; d > 0; d >>= 1) acc[g] += __shfl_xor_sync(0xFFFFFFFFu, acc[g], d);
    }
    if (lane < 8) g_gates[(size_t)t*8 + lane] = acc[lane] + bif[lane];
}

// ================= shared GEMM machinery (128-row tiles) =================
#define TSTR 40
#define OFF_AH 0
#define OFF_AL 10240
#define OFF_BH 20480
#define STAGE_B 30720
#define GEMM_SMEM (2*STAGE_B)

struct GemmCtx {
    uint32_t aoff[2][2], boff[4][2];
    uint32_t soA, soB;
    int wm, wn, lane;
};
__device__ __forceinline__ void gemm_init(GemmCtx& c, int tid) {
    int warp = tid >> 5; c.lane = tid & 31;
    c.wm = warp >> 1; c.wn = warp & 1;
#pragma unroll
    for (int mt = 0; mt < 2; mt++)
#pragma unroll
        for (int ks = 0; ks < 2; ks++)
            c.aoff[mt][ks] = ((c.wm*32 + mt*16 + (c.lane & 15))*TSTR + ks*16 + ((c.lane >> 4) << 3))*2;
#pragma unroll
    for (int ntp = 0; ntp < 4; ntp++)
#pragma unroll
        for (int ks = 0; ks < 2; ks++)
            c.boff[ntp][ks] = ((c.wn*64 + ntp*16 + ((c.lane >> 4) << 3) + (c.lane & 7))*TSTR
                               + ks*16 + (((c.lane >> 3) & 1) << 3))*2;
    int ldRow = tid >> 2, ldQuad = tid & 3;
    c.soA = (ldRow*TSTR + ldQuad*8)*2;
    c.soB = ((ldRow+64)*TSTR + ldQuad*8)*2;
}
__device__ __forceinline__ void gemm_stage(const GemmCtx& c, uint32_t st, int tid,
                                           const __half* Ah0, const __half* Al0, int lda,
                                           const __half* Bh0, int K, int k0) {
    int ldRow = tid >> 2, ldQuad = tid & 3;
    cpa16(st + OFF_AH + c.soA, Ah0 + (size_t)ldRow*lda + k0 + ldQuad*8);
    cpa16(st + OFF_AL + c.soA, Al0 + (size_t)ldRow*lda + k0 + ldQuad*8);
    cpa16(st + OFF_BH + c.soA, Bh0 + (size_t)ldRow*K + k0 + ldQuad*8);
    cpa16(st + OFF_AH + c.soB, Ah0 + (size_t)(ldRow+64)*lda + k0 + ldQuad*8);
    cpa16(st + OFF_AL + c.soB, Al0 + (size_t)(ldRow+64)*lda + k0 + ldQuad*8);
    cpa16(st + OFF_BH + c.soB, Bh0 + (size_t)(ldRow+64)*K + k0 + ldQuad*8);
    CP_COMMIT();
}
__device__ __forceinline__ void gemm_math(const GemmCtx& c, uint32_t st, float acc[2][8][4]) {
    uint32_t sAh_b = st + OFF_AH, sAl_b = st + OFF_AL, sBh_b = st + OFF_BH;
#pragma unroll
    for (int ks = 0; ks < 2; ks++) {
        uint32_t ah[2][4], al[2][4], bh[4][4];
#pragma unroll
        for (int mt = 0; mt < 2; mt++) {
            ldmx4(ah[mt], sAh_b + c.aoff[mt][ks]);
            ldmx4(al[mt], sAl_b + c.aoff[mt][ks]);
        }
#pragma unroll
        for (int ntp = 0; ntp < 4; ntp++)
            ldmx4(bh[ntp], sBh_b + c.boff[ntp][ks]);
#pragma unroll
        for (int mt = 0; mt < 2; mt++)
#pragma unroll
            for (int nt = 0; nt < 8; nt++) {
                int p = nt >> 1, hh = (nt & 1) * 2;
                mma16816(acc[mt][nt], ah[mt], &bh[p][hh]);
                mma16816(acc[mt][nt], al[mt], &bh[p][hh]);
            }
    }
}

// MODE: 2 fp32 + hi/lo split for col<DI (up-GEMM)
template<int MODE>
__global__ void __launch_bounds__(256)
mmagemm2_kernel(const __half* __restrict__ Ah, const __half* __restrict__ Al, int lda,
                const __half* __restrict__ Bh,
                const float* __restrict__ bias, const float* __restrict__ resid,
                float* __restrict__ C, int ldc,
                __half* __restrict__ Ohi, __half* __restrict__ Olo, int ldo,
                int K) {
    extern __shared__ char dsm[];
    uint32_t sb = smem_u32(dsm);
    int tid = threadIdx.x;
    GemmCtx c; gemm_init(c, tid);
    int rowBase = blockIdx.x * 128;
    int colBase = blockIdx.y * 128;
    const __half* Ah0 = Ah + (size_t)rowBase*lda;
    const __half* Al0 = Al + (size_t)rowBase*lda;
    const __half* Bh0 = Bh + (size_t)colBase*K;

    float acc[2][8][4];
#pragma unroll
    for (int mt = 0; mt < 2; mt++)
#pragma unroll
        for (int nt = 0; nt < 8; nt++)
#pragma unroll
            for (int i = 0; i < 4; i++) acc[mt][nt][i] = 0.f;

    int nch = K >> 5;
    gemm_stage(c, sb, tid, Ah0, Al0, lda, Bh0, K, 0);
    int buf = 0;
    for (int ch = 0; ch < nch; ch++) {
        CP_WAIT0();
        __syncthreads();
        if (ch + 1 < nch)
            gemm_stage(c, sb + (buf^1)*STAGE_B, tid, Ah0, Al0, lda, Bh0, K, (ch+1) << 5);
        gemm_math(c, sb + buf*STAGE_B, acc);
        buf ^= 1;
        __syncthreads();
    }

    int r0b = rowBase + c.wm*32 + (c.lane >> 2);
    int cb  = colBase + c.wn*64 + (c.lane & 3)*2;
#pragma unroll
    for (int mt = 0; mt < 2; mt++) {
#pragma unroll
        for (int nt = 0; nt < 8; nt++) {
            int col = cb + nt*8;
#pragma unroll
            for (int half = 0; half < 2; half++) {
                int row = r0b + mt*16 + half*8;
                float vx = acc[mt][nt][half*2+0];
                float vy = acc[mt][nt][half*2+1];
                if (bias) { vx += bias[col]; vy += bias[col+1]; }
                if (MODE == 0 && resid) {
                    const float2 r2 = *(const float2*)(resid + (size_t)row*ldc + col);
                    vx += r2.x; vy += r2.y;
                }
                float2 o; o.x = vx; o.y = vy;
                *(float2*)(C + (size_t)row*ldc + col) = o;
                if (MODE == 2 && col < DI) {
                    __half hx = __float2half_rn(vx);
                    __half hy = __float2half_rn(vy);
                    __half2 hv; hv.x = hx; hv.y = hy;
                    __half2 lv;
                    lv.x = __float2half_rn(vx - __half2float(hx));
                    lv.y = __float2half_rn(vy - __half2float(hy));
                    *(__half2*)(Ohi + (size_t)row*ldo + col) = hv;
                    *(__half2*)(Olo + (size_t)row*ldo + col) = lv;
                }
            }
        }
    }
}

// ---------------- down-GEMM: 64x128 tiles ----------------
#define D64_AH 0
#define D64_AL 5120
#define D64_BH 10240
#define D64_STAGE 20480
#define D64_SMEM (2*D64_STAGE)

__global__ void __launch_bounds__(256)
dngemm_kernel(const __half* __restrict__ Ah, const __half* __restrict__ Al,
              const __half* __restrict__ Bh, const float* __restrict__ bias,
              float* __restrict__ C) {
    extern __shared__ char dsm[];
    uint32_t sb = smem_u32(dsm);
    int tid = threadIdx.x;
    int warp = tid >> 5, lane = tid & 31;
    int wm = warp >> 1, wn = warp & 1;
    int rowBase = blockIdx.x * 64;
    int colBase = blockIdx.y * 128;
    const __half* Ah0 = Ah + (size_t)rowBase*DI;
    const __half* Al0 = Al + (size_t)rowBase*DI;
    const __half* Bh0 = Bh + (size_t)colBase*DI;

    float acc[8][4];
#pragma unroll
    for (int nt = 0; nt < 8; nt++)
#pragma unroll
        for (int i = 0; i < 4; i++) acc[nt][i] = 0.f;

    uint32_t aoff[2], boff[4][2];
#pragma unroll
    for (int ks = 0; ks < 2; ks++)
        aoff[ks] = ((wm*16 + (lane & 15))*TSTR + ks*16 + ((lane >> 4) << 3))*2;
#pragma unroll
    for (int ntp = 0; ntp < 4; ntp++)
#pragma unroll
        for (int ks = 0; ks < 2; ks++)
            boff[ntp][ks] = ((wn*64 + ntp*16 + ((lane >> 4) << 3) + (lane & 7))*TSTR
                             + ks*16 + (((lane >> 3) & 1) << 3))*2;

    int arow = tid >> 2, aq = tid & 3;
    uint32_t soA = (arow*TSTR + aq*8)*2;
    int brow = tid >> 1, bq = (tid & 1)*2;
    uint32_t soB0 = (brow*TSTR + bq*8)*2;
    uint32_t soB1 = (brow*TSTR + (bq+1)*8)*2;

    {
        uint32_t st = sb;
        cpa16(st + D64_AH + soA, Ah0 + (size_t)arow*DI + aq*8);
        cpa16(st + D64_AL + soA, Al0 + (size_t)arow*DI + aq*8);
        cpa16(st + D64_BH + soB0, Bh0 + (size_t)brow*DI + bq*8);
        cpa16(st + D64_BH + soB1, Bh0 + (size_t)brow*DI + (bq+1)*8);
        CP_COMMIT();
    }
    int buf = 0;
    for (int ch = 0; ch < 16; ch++) {
        CP_WAIT0();
        __syncthreads();
        if (ch + 1 < 16) {
            int k1 = (ch + 1) << 5;
            uint32_t st = sb + (buf^1)*D64_STAGE;
            cpa16(st + D64_AH + soA, Ah0 + (size_t)arow*DI + k1 + aq*8);
            cpa16(st + D64_AL + soA, Al0 + (size_t)arow*DI + k1 + aq*8);
            cpa16(st + D64_BH + soB0, Bh0 + (size_t)brow*DI + k1 + bq*8);
            cpa16(st + D64_BH + soB1, Bh0 + (size_t)brow*DI + k1 + (bq+1)*8);
            CP_COMMIT();
        }
        uint32_t st = sb + buf*D64_STAGE;
#pragma unroll
        for (int ks = 0; ks < 2; ks++) {
            uint32_t ah[4], al[4], bh[4][4];
            ldmx4(ah, st + D64_AH + aoff[ks]);
            ldmx4(al, st + D64_AL + aoff[ks]);
#pragma unroll
            for (int ntp = 0; ntp < 4; ntp++)
                ldmx4(bh[ntp], st + D64_BH + boff[ntp][ks]);
#pragma unroll
            for (int nt = 0; nt < 8; nt++) {
                int p = nt >> 1, hh = (nt & 1) * 2;
                mma16816(acc[nt], ah, &bh[p][hh]);
                mma16816(acc[nt], al, &bh[p][hh]);
            }
        }
        buf ^= 1;
        __syncthreads();
    }

    int r0b = rowBase + wm*16 + (lane >> 2);
    int cb  = colBase + wn*64 + (lane & 3)*2;
#pragma unroll
    for (int nt = 0; nt < 8; nt++) {
        int col = cb + nt*8;
#pragma unroll
        for (int half = 0; half < 2; half++) {
            int row = r0b + half*8;
            float vx = acc[nt][half*2+0] + bias[col];
            float vy = acc[nt][half*2+1] + bias[col+1];
            float2 r2 = *(const float2*)(C + (size_t)row*D + col);
            vx += r2.x; vy += r2.y;
            float2 o; o.x = vx; o.y = vy;
            *(float2*)(C + (size_t)row*D + col) = o;
        }
    }
}

// ---------------- fused Q/K/V GEMM (all hi-only outputs now) ----------------
__global__ void __launch_bounds__(256)
qkvgemm_kernel(const __half* __restrict__ wt) {
    extern __shared__ char dsm[];
    uint32_t sb = smem_u32(dsm);
    int tid = threadIdx.x;
    GemmCtx c; gemm_init(c, tid);
    int rowBase = blockIdx.x * 128;
    int yb = blockIdx.y;
    int sel = yb >> 2;
    int colBase = (yb & 3) * 128;

    const __half* Ah = (sel == 2) ? g_xm_h : g_xc_h;
    const __half* Al = (sel == 2) ? g_xm_l : g_xc_l;
    const __half* Bh0 = wt + (sel == 0 ? WT_Q_OFF : sel == 1 ? WT_K_OFF : WT_V_OFF)
                      + (size_t)colBase*DI;
    const __half* Ah0 = Ah + (size_t)rowBase*DI;
    const __half* Al0 = Al + (size_t)rowBase*DI;

    float acc[2][8][4];
#pragma unroll
    for (int mt = 0; mt < 2; mt++)
#pragma unroll
        for (int nt = 0; nt < 8; nt++)
#pragma unroll
            for (int i = 0; i < 4; i++) acc[mt][nt][i] = 0.f;

    gemm_stage(c, sb, tid, Ah0, Al0, DI, Bh0, DI, 0);
    int buf = 0;
    for (int ch = 0; ch < 16; ch++) {
        CP_WAIT0();
        __syncthreads();
        if (ch + 1 < 16)
            gemm_stage(c, sb + (buf^1)*STAGE_B, tid, Ah0, Al0, DI, Bh0, DI, (ch+1) << 5);
        gemm_math(c, sb + buf*STAGE_B, acc);
        buf ^= 1;
        __syncthreads();
    }

    __half* Ohi = (sel == 0) ? g_qh : (sel == 1) ? g_kh : g_vh;
    int r0b = rowBase + c.wm*32 + (c.lane >> 2);
    int cb  = colBase + c.wn*64 + (c.lane & 3)*2;
#pragma unroll
    for (int mt = 0; mt < 2; mt++) {
#pragma unroll
        for (int nt = 0; nt < 8; nt++) {
            int col = cb + nt*8;
#pragma unroll
            for (int half = 0; half < 2; half++) {
                int row = r0b + mt*16 + half*8;
                __half2 hv;
                hv.x = __float2half_rn(acc[mt][nt][half*2+0]);
                hv.y = __float2half_rn(acc[mt][nt][half*2+1]);
                *(__half2*)(Ohi + (size_t)row*DI + col) = hv;
            }
        }
    }
}

// ---------------- conv + SiLU ----------------
__global__ void conv_kernel(const float* __restrict__ w, const float* __restrict__ bias) {
    int idx = blockIdx.x * blockDim.x + threadIdx.x;
    int c = idx % DI;
    int t = idx / DI;
    int s = t % SS;
    float acc = bias[c];
#pragma unroll
    for (int j = 0; j < KC; j++) {
        int ss = s - 3 + j;
        if (ss >= 0) acc += g_up[(size_t)(t - 3 + j)*2*DI + c] * w[j*DI + c];
    }
    float y = acc / (1.f + __expf(-acc));
    g_xc[idx] = y;
    __half h = __float2half_rn(y);
    g_xc_h[idx] = h;
    g_xc_l[idx] = __float2half_rn(y - __half2float(h));
}

// ---------------- gate scan: smem preload + warp scan ----------------
__global__ void __launch_bounds__(256) gatescan_kernel() {
    __shared__ float sif[SS], sff[SS];
    int bh = blockIdx.x;
    int b = bh >> 2, h = bh & 3;
    int tid = threadIdx.x;
    for (int i = tid; i < SS; i += 256) {
        const float* gp = g_gates + (size_t)(b*SS + i)*8;
        sif[i] = gp[h];
        sff[i] = gp[NH + h];
    }
    __syncthreads();
    if (tid < 32) {
        int lane = tid;
        float carryF = 0.f, carryM = -1e30f;
        for (int c = 0; c < SS/32; c++) {
            int t = c*32 + lane;
            float fp = sff[t], ipv = sif[t];
            float lf = (fp >= 0.f) ? -log1pf(__expf(-fp)) : fp - log1pf(__expf(fp));
            float s = lf;
#pragma unroll
            for (int d = 1; d < 32; d <<= 1) {
                float v = __shfl_up_sync(0xFFFFFFFFu, s, d);
                if (lane >= d) s += v;
            }
            float Fc = carryF + s;
            float bt = ipv - Fc;
            float mx = bt;
#pragma unroll
            for (int d = 1; d < 32; d <<= 1) {
                float v = __shfl_up_sync(0xFFFFFFFFu, mx, d);
                if (lane >= d) mx = fmaxf(mx, v);
            }
            float rmax = fmaxf(carryM, mx);
            g_beta [bh*SS + t] = bt;
            g_alpha[bh*SS + t] = -rmax;
            g_m    [bh*SS + t] = Fc + rmax;
            carryF += __shfl_sync(0xFFFFFFFFu, s, 31);
            carryM  = fmaxf(carryM, __shfl_sync(0xFFFFFFFFu, rmax, 31));
        }
    }
}

// ================= fp16 attention: single-pass S and AV, heavy-first =================
#define STRQ 136
#define STRV 40
#define A2_QH 0
#define A2_KH (A2_QH + 128*STRQ*2)
#define A2_VH (A2_KH + 32*STRQ*2)
#define A2_BT (A2_VH + 128*STRV*2)
#define ATTN2_SMEM (A2_BT + 32*4)
#define SCALE 0.08838834764831845f

__global__ void __launch_bounds__(256) attn2_kernel() {
    extern __shared__ char sm2[];
    __half* Qh = (__half*)(sm2 + A2_QH);
    __half* Kh = (__half*)(sm2 + A2_KH);
    __half* Vh = (__half*)(sm2 + A2_VH);
    float* bts = (float*)(sm2 + A2_BT);

    int xw = blockIdx.x;
    int qt = 7 - (xw >> 1);
    int sh = xw & 1;
    int bh = blockIdx.y;
    int b = bh >> 2, h = bh & 3;
    int tid = threadIdx.x, warp = tid >> 5, lane = tid & 31;
    int t0 = qt * 128;

#pragma unroll
    for (int j = 0; j < 8; j++) {
        int i = tid + j*256;
        int row = i >> 4, c8 = (i & 15)*8;
        size_t gb = (size_t)(b*SS + t0 + row)*DI + h*DH + c8;
        *(uint4*)(Qh + row*STRQ + c8) = *(const uint4*)(g_qh + gb);
    }

    int tr0 = t0 + warp*16 + (lane >> 2);
    int tr1 = tr0 + 8;
    float al0 = g_alpha[bh*SS + tr0];
    float al1 = g_alpha[bh*SS + tr1];

    float O[16][4];
#pragma unroll
    for (int nt = 0; nt < 16; nt++)
#pragma unroll
        for (int i = 0; i < 4; i++) O[nt][i] = 0.f;
    float rs0 = 0.f, rs1 = 0.f;

    uint32_t sQh = smem_u32(Qh);
    uint32_t sKh = smem_u32(Kh), sVh = smem_u32(Vh);

    uint32_t qoff[8], koff[2][8], voff[8][2];
#pragma unroll
    for (int ks = 0; ks < 8; ks++)
        qoff[ks] = ((warp*16 + (lane & 15))*STRQ + ks*16 + ((lane >> 4) << 3))*2;
#pragma unroll
    for (int np = 0; np < 2; np++)
#pragma unroll
        for (int ks = 0; ks < 8; ks++)
            koff[np][ks] = ((np*16 + ((lane >> 4) << 3) + (lane & 7))*STRQ
                            + ks*16 + (((lane >> 3) & 1) << 3))*2;
#pragma unroll
    for (int np = 0; np < 8; np++)
#pragma unroll
        for (int kv = 0; kv < 2; kv++)
            voff[np][kv] = ((np*16 + ((lane >> 4) << 3) + (lane & 7))*STRV
                            + kv*16 + (((lane >> 3) & 1) << 3))*2;

    int half_tiles = 2*(qt + 1);
    int st_lo = sh * half_tiles;
    int st_hi = st_lo + half_tiles;
    for (int st = st_lo; st < st_hi; st++) {
        int s0 = st * 32;
        __syncthreads();
#pragma unroll
        for (int j = 0; j < 2; j++) {
            int i = tid + j*256;
            int row = i >> 4, c8 = (i & 15)*8;
            size_t gb = (size_t)(b*SS + s0 + row)*DI + h*DH + c8;
            *(uint4*)(Kh + row*STRQ + c8) = *(const uint4*)(g_kh + gb);
            uint4 vh4 = *(const uint4*)(g_vh + gb);
            const __half* vhp = (const __half*)&vh4;
#pragma unroll
            for (int e = 0; e < 8; e++)
                Vh[(c8+e)*STRV + row] = vhp[e];
        }
        if (tid < 32) bts[tid] = g_beta[bh*SS + s0 + tid];
        __syncthreads();

        float S[4][4];
#pragma unroll
        for (int nt = 0; nt < 4; nt++)
#pragma unroll
            for (int i = 0; i < 4; i++) S[nt][i] = 0.f;
#pragma unroll
        for (int ks = 0; ks < 8; ks++) {
            uint32_t ah[4], bkh[2][4];
            ldmx4(ah, sQh + qoff[ks]);
            ldmx4(bkh[0], sKh + koff[0][ks]);
            ldmx4(bkh[1], sKh + koff[1][ks]);
#pragma unroll
            for (int nt = 0; nt < 4; nt++) {
                int p = nt >> 1, hh = (nt & 1)*2;
                mma16816(S[nt], ah, &bkh[p][hh]);
            }
        }

        uint32_t Ph[2][4];
#pragma unroll
        for (int nt = 0; nt < 4; nt++) {
            float pv[4];
#pragma unroll
            for (int r = 0; r < 4; r++) {
                int trow = (r < 2) ? tr0 : tr1;
                float alv = (r < 2) ? al0 : al1;
                int cl = nt*8 + (lane & 3)*2 + (r & 1);
                int sc = s0 + cl;
                float w = (sc <= trow) ? __expf(alv + bts[cl]) : 0.f;
                float p = S[nt][r] * SCALE * w;
                if (r < 2) rs0 += p; else rs1 += p;
                pv[r] = p;
            }
            int kv = nt >> 1;
            if ((nt & 1) == 0) {
                Ph[kv][0] = packh2(pv[0], pv[1]);
                Ph[kv][1] = packh2(pv[2], pv[3]);
            } else {
                Ph[kv][2] = packh2(pv[0], pv[1]);
                Ph[kv][3] = packh2(pv[2], pv[3]);
            }
        }

#pragma unroll
        for (int kv = 0; kv < 2; kv++) {
#pragma unroll
            for (int np = 0; np < 8; np++) {
                uint32_t bvh[4];
                ldmx4(bvh, sVh + voff[np][kv]);
#pragma unroll
                for (int hh = 0; hh < 2; hh++)
                    mma16816(O[np*2 + hh], Ph[kv], &bvh[hh*2]);
            }
        }
    }

    rs0 += __shfl_xor_sync(0xFFFFFFFFu, rs0, 1);
    rs0 += __shfl_xor_sync(0xFFFFFFFFu, rs0, 2);
    rs1 += __shfl_xor_sync(0xFFFFFFFFu, rs1, 1);
    rs1 += __shfl_xor_sync(0xFFFFFFFFu, rs1, 2);
    if ((lane & 3) == 0) {
        g_rs[sh*NBH*SS + bh*SS + tr0] = rs0;
        g_rs[sh*NBH*SS + bh*SS + tr1] = rs1;
    }

    float* o0 = g_htp + (size_t)sh*NT*DI + (size_t)(b*SS + tr0)*DI + h*DH + (lane & 3)*2;
    float* o1 = g_htp + (size_t)sh*NT*DI + (size_t)(b*SS + tr1)*DI + h*DH + (lane & 3)*2;
#pragma unroll
    for (int nt = 0; nt < 16; nt++) {
        float2 v0; v0.x = O[nt][0]; v0.y = O[nt][1];
        float2 v1; v1.x = O[nt][2]; v1.y = O[nt][3];
        *(float2*)(o0 + nt*8) = v0;
        *(float2*)(o1 + nt*8) = v1;
    }
}

// ---------------- combine partials + per-head LN + skip + SiLU gate ----------------
__global__ void gnmerge_kernel(const float* __restrict__ gn_g, const float* __restrict__ gn_b,
                               const float* __restrict__ skip) {
    int t = blockIdx.x, tid = threadIdx.x;
    __shared__ float red[512];
    int l = tid & 127;
    int gbase = (tid >> 7) << 7;
    int b = t >> 10, s = t & 1023;
    int h = tid >> 7;
    int bh = b*NH + h;
    float rs = g_rs[bh*SS + s] + g_rs[NBH*SS + bh*SS + s];
    float me = __expf(-g_m[bh*SS + s]);
    float inv = 1.f / (fmaxf(fabsf(rs), me) + 1e-6f);
    float v = (g_htp[(size_t)t*DI + tid] + g_htp[(size_t)NT*DI + (size_t)t*DI + tid]) * inv;
    red[tid] = v; __syncthreads();
    for (int off = 64; off > 0; off >>= 1) { if (l < off) red[tid] += red[tid+off]; __syncthreads(); }
    float mean = red[gbase] * (1.f/128.f); __syncthreads();
    float c = v - mean;
    red[tid] = c*c; __syncthreads();
    for (int off = 64; off > 0; off >>= 1) { if (l < off) red[tid] += red[tid+off]; __syncthreads(); }
    float var = red[gbase] * (1.f/128.f);
    float y = c * rsqrtf(var + 1e-5f) * gn_g[tid] + gn_b[tid];
    y += skip[tid] * g_xc[(size_t)t*DI + tid];
    float z = g_up[(size_t)t*2*DI + DI + tid];
    y *= z / (1.f + __expf(-z));
    __half hh = __float2half_rn(y);
    g_mix_h[(size_t)t*DI + tid] = hh;
    g_mix_l[(size_t)t*DI + tid] = __float2half_rn(y - __half2float(hh));
}

// ---------------- final LN + projection ----------------
__global__ void final_kernel(const float* __restrict__ lnf_g, const float* __restrict__ lnf_b,
                             const float* __restrict__ Wf, const float* __restrict__ bf,
                             float* __restrict__ out) {
    int b = blockIdx.x, tid = threadIdx.x;
    __shared__ float red[256];
    float v = g_h[(size_t)(b*SS + SS - 1)*D + tid];
    red[tid] = v; __syncthreads();
    for (int off = 128; off > 0; off >>= 1) { if (tid < off) red[tid] += red[tid+off]; __syncthreads(); }
    float mean = red[0] * (1.f/256.f); __syncthreads();
    float c = v - mean;
    red[tid] = c*c; __syncthreads();
    for (int off = 128; off > 0; off >>= 1) { if (tid < off) red[tid] += red[tid+off]; __syncthreads(); }
    float var = red[0] * (1.f/256.f); __syncthreads();
    float y = c * rsqrtf(var + 1e-5f) * lnf_g[tid] + lnf_b[tid];
    red[tid] = y * Wf[tid]; __syncthreads();
    for (int off = 128; off > 0; off >>= 1) { if (tid < off) red[tid] += red[tid+off]; __syncthreads(); }
    if (tid == 0) out[b] = red[0] + bf[0];
}

// ---------------- host ----------------
static float* symaddrf(const void* sym) {
    void* p = nullptr;
    cudaGetSymbolAddress(&p, sym);
    return (float*)p;
}
static __half* symaddrh(const void* sym) {
    void* p = nullptr;
    cudaGetSymbolAddress(&p, sym);
    return (__half*)p;
}

extern "C" void kernel_launch(void* const* d_in, const int* in_sizes, int n_in,
                              void* d_out, int out_size) {
    const float* x      = (const float*)d_in[0];
    const float* tf     = (const float*)d_in[1];
    const float* Wp     = (const float*)d_in[2];
    const float* bp     = (const float*)d_in[3];
    const float* ln_g   = (const float*)d_in[4];
    const float* ln_b   = (const float*)d_in[5];
    const float* Wup    = (const float*)d_in[6];
    const float* bup    = (const float*)d_in[7];
    const float* conv_w = (const float*)d_in[8];
    const float* conv_b = (const float*)d_in[9];
    const float* Wq     = (const float*)d_in[10];
    const float* Wk     = (const float*)d_in[11];
    const float* Wv     = (const float*)d_in[12];
    const float* Wif    = (const float*)d_in[13];
    const float* bif    = (const float*)d_in[14];
    const float* gn_g   = (const float*)d_in[15];
    const float* gn_b   = (const float*)d_in[16];
    const float* skip   = (const float*)d_in[17];
    const float* Wdown  = (const float*)d_in[18];
    const float* bdown  = (const float*)d_in[19];
    const float* lnf_g  = (const float*)d_in[20];
    const float* lnf_b  = (const float*)d_in[21];
    const float* Wf     = (const float*)d_in[22];
    const float* bf     = (const float*)d_in[23];
    float* out = (float*)d_out;

    float* p_h   = symaddrf(g_h);
    float* p_up  = symaddrf(g_up);
    float* p_wc  = symaddrf(g_wc);
    __half* p_hn_h = symaddrh(g_hn_h);
    __half* p_hn_l = symaddrh(g_hn_l);
    __half* p_xm_h = symaddrh(g_xm_h);
    __half* p_xm_l = symaddrh(g_xm_l);
    __half* p_mix_h = symaddrh(g_mix_h);
    __half* p_mix_l = symaddrh(g_mix_l);
    __half* p_wt_h = symaddrh(g_wt_h);

    cudaFuncSetAttribute(attn2_kernel, cudaFuncAttributeMaxDynamicSharedMemorySize, ATTN2_SMEM);
    cudaFuncSetAttribute(mmagemm2_kernel<2>, cudaFuncAttributeMaxDynamicSharedMemorySize, GEMM_SMEM);
    cudaFuncSetAttribute(qkvgemm_kernel, cudaFuncAttributeMaxDynamicSharedMemorySize, GEMM_SMEM);
    cudaFuncSetAttribute(dngemm_kernel, cudaFuncAttributeMaxDynamicSharedMemorySize, D64_SMEM);

    dim3 wblk(32, 8);
    wsplit_all<<<dim3(D/32, 2*DI/32, NL), wblk>>>(Wup, (long)D*2*DI, D, 2*DI,
                                                  p_wt_h + WT_UP_OFF, WT_L);
    wsplit_all<<<dim3(DI/32, DI/32, NL), wblk>>>(Wq, (long)DI*DI, DI, DI,
                                                 p_wt_h + WT_Q_OFF, WT_L);
    wsplit_all<<<dim3(DI/32, DI/32, NL), wblk>>>(Wk, (long)DI*DI, DI, DI,
                                                 p_wt_h + WT_K_OFF, WT_L);
    wsplit_all<<<dim3(DI/32, DI/32, NL), wblk>>>(Wv, (long)DI*DI, DI, DI,
                                                 p_wt_h + WT_V_OFF, WT_L);
    wsplit_all<<<dim3(DI/32, D/32, NL), wblk>>>(Wdown, (long)DI*D, DI, D,
                                                p_wt_h + WT_DN_OFF, WT_L);
    wcomb_kernel<<<dim3(DI, NL), 256>>>(Wq, Wk, Wv, Wif, p_wc);

    embed_kernel<<<NT, 256>>>(x, tf, Wp, bp);

    for (int l = 0; l < NL; l++) {
        size_t wo = (size_t)l * WT_L;
        ln256_kernel<<<NT, 256>>>(p_h, ln_g + l*D, ln_b + l*D);

        mmagemm2_kernel<2><<<dim3(NT/128, 1024/128), 256, GEMM_SMEM>>>(
            p_hn_h, p_hn_l, D, p_wt_h + wo + WT_UP_OFF,
            bup + l*2*DI, nullptr, p_up, 2*DI, p_xm_h, p_xm_l, DI, D);

        conv_kernel<<<NT*DI/256, 256>>>(conv_w + l*KC*DI, conv_b + l*DI);

        qkvgemm_kernel<<<dim3(NT/128, 12), 256, GEMM_SMEM>>>(p_wt_h + wo);

        gates2_kernel<<<NT/8, 256>>>(p_wc + (size_t)l*DI*16, bif + l*2*NH);
        gatescan_kernel<<<NBH, 256>>>();

        attn2_kernel<<<dim3(16, NBH), 256, ATTN2_SMEM>>>();

        gnmerge_kernel<<<NT, 512>>>(gn_g + l*DI, gn_b + l*DI, skip + l*DI);

        dngemm_kernel<<<dim3(NT/64, D/128), 256, D64_SMEM>>>(
            p_mix_h, p_mix_l, p_wt_h + wo + WT_DN_OFF, bdown + l*D, p_h);
    }

    final_kernel<<<NB, 256>>>(lnf_g, lnf_b, Wf, bf, out);
}